// round 7
// baseline (speedup 1.0000x reference)
#include <cuda_runtime.h>
#include <cuda_fp16.h>
#include <cstdint>

// SNNAutoencoder: B=65536, D=512, H=64, L=16, T=8
// Inputs: x[65536,512], W1[64,512], b1[64], W2[16,64], b2[16],
//         W3[64,16], b3[64], W4[512,64], b4[512]    Output: float32 [65536,512]

#define B_TOTAL 65536

// Scratch (static device arrays)
__device__ float              g_hin[(size_t)B_TOTAL * 64];      // 16 MB
__device__ unsigned long long g_masks[(size_t)B_TOTAL * 8];     //  4 MB packed s3
__device__ unsigned           g_w4f[512 * 32];                  // fp16x2 (0.5*W4) [c][kpair]
__device__ float4             g_w1p[64 * 64 * 4];               // tf32 (hi0,hi4,lo0,lo4)

// ---------------------------------------------------------------------------
// helpers
// ---------------------------------------------------------------------------
__device__ __forceinline__ unsigned tanh2(unsigned h) {
    unsigned r;
    asm("tanh.approx.f16x2 %0, %1;" : "=r"(r) : "r"(h));
    return r;
}
__device__ __forceinline__ unsigned cvt_tf32(float f) {
    unsigned u;
    asm("cvt.rna.tf32.f32 %0, %1;" : "=r"(u) : "f"(f));
    return u;
}
__device__ __forceinline__ uint32_t smem_u32(const void* p) {
    uint32_t a;
    asm("{ .reg .u64 t; cvta.to.shared.u64 t, %1; cvt.u32.u64 %0, t; }" : "=r"(a) : "l"(p));
    return a;
}
__device__ __forceinline__ void cpa16(uint32_t dst, const void* src) {
    asm volatile("cp.async.ca.shared.global [%0], [%1], 16;" :: "r"(dst), "l"(src));
}
#define CPA_COMMIT() asm volatile("cp.async.commit_group;" ::: "memory")
#define CPA_WAIT0()  asm volatile("cp.async.wait_group 0;" ::: "memory")

// fp16 mma with explicit C operand (bias init): D = A*B + C
__device__ __forceinline__ void mma16816h_c(float* d, const unsigned* a,
                                            unsigned b0, unsigned b1,
                                            float c0, float c1, float c2, float c3) {
    asm volatile(
        "mma.sync.aligned.m16n8k16.row.col.f32.f16.f16.f32 "
        "{%0,%1,%2,%3}, {%4,%5,%6,%7}, {%8,%9}, {%10,%11,%12,%13};"
        : "=f"(d[0]), "=f"(d[1]), "=f"(d[2]), "=f"(d[3])
        : "r"(a[0]), "r"(a[1]), "r"(a[2]), "r"(a[3]), "r"(b0), "r"(b1),
          "f"(c0), "f"(c1), "f"(c2), "f"(c3));
}
__device__ __forceinline__ void mma16816h(float* d, const unsigned* a,
                                          unsigned b0, unsigned b1) {
    asm volatile(
        "mma.sync.aligned.m16n8k16.row.col.f32.f16.f16.f32 "
        "{%0,%1,%2,%3}, {%4,%5,%6,%7}, {%8,%9}, {%0,%1,%2,%3};"
        : "+f"(d[0]), "+f"(d[1]), "+f"(d[2]), "+f"(d[3])
        : "r"(a[0]), "r"(a[1]), "r"(a[2]), "r"(a[3]), "r"(b0), "r"(b1));
}
// tf32 mma
__device__ __forceinline__ void mma1688t(float* d, const unsigned* a,
                                         unsigned b0, unsigned b1) {
    asm volatile(
        "mma.sync.aligned.m16n8k8.row.col.f32.tf32.tf32.f32 "
        "{%0,%1,%2,%3}, {%4,%5,%6,%7}, {%8,%9}, {%0,%1,%2,%3};"
        : "+f"(d[0]), "+f"(d[1]), "+f"(d[2]), "+f"(d[3])
        : "r"(a[0]), "r"(a[1]), "r"(a[2]), "r"(a[3]), "r"(b0), "r"(b1));
}

// ---------------------------------------------------------------------------
// Kernel 0: pack 0.5*W4 (fp16x2) and W1 (tf32 hi/lo float4 interleaved)
// ---------------------------------------------------------------------------
__global__ void k0_pack(const float* __restrict__ W4,
                        const float* __restrict__ W1) {
    const int bid = blockIdx.x;
    const int idx = (bid & 63) * 256 + threadIdx.x;   // 0..16383
    if (bid < 64) {
        float w0 = 0.5f * W4[2 * idx], w1 = 0.5f * W4[2 * idx + 1];
        __half h0 = __float2half_rn(w0);
        __half h1 = __float2half_rn(w1);
        g_w4f[idx] = (unsigned)__half_as_ushort(h0) |
                     ((unsigned)__half_as_ushort(h1) << 16);
    } else {
        int ks = idx >> 8, n = (idx >> 2) & 63, q = idx & 3;
        float w0 = W1[n * 512 + ks * 8 + q];
        float w4 = W1[n * 512 + ks * 8 + q + 4];
        unsigned h0 = cvt_tf32(w0), h4 = cvt_tf32(w4);
        unsigned l0 = cvt_tf32(w0 - __uint_as_float(h0));
        unsigned l4 = cvt_tf32(w4 - __uint_as_float(h4));
        g_w1p[idx] = make_float4(__uint_as_float(h0), __uint_as_float(h4),
                                 __uint_as_float(l0), __uint_as_float(l4));
    }
}

// ---------------------------------------------------------------------------
// Kernel 1: h_in = x @ W1^T + b1 via 3xTF32 mma.sync (fp32-equivalent).
// x + W1 frags staged via cp.async; W1 frags packed float4 (1 LDS.128 each).
// ---------------------------------------------------------------------------
__global__ void __launch_bounds__(256) k1_hin(const float* __restrict__ x,
                                              const float* __restrict__ b1) {
    extern __shared__ float smemf[];
    float*  xs = smemf;                       // [128][68]  34816 B
    float4* wp = (float4*)(smemf + 8704);     // [2048]     32768 B

    const int tid = threadIdx.x;
    const int warp = tid >> 5, lane = tid & 31;
    const int g = lane >> 2, q = lane & 3;
    const int blockRow = blockIdx.x * 128;

    const uint32_t xs_a = smem_u32(xs);
    const uint32_t wp_a = smem_u32(wp);

    float d[8][4];
#pragma unroll
    for (int j = 0; j < 8; j++)
#pragma unroll
        for (int i = 0; i < 4; i++) d[j][i] = 0.0f;

    const int r0 = warp * 16 + g;
    const int r1 = r0 + 8;

    for (int ch = 0; ch < 8; ch++) {
        __syncthreads();
        const float* xsrc = x + (size_t)blockRow * 512 + ch * 64;
#pragma unroll
        for (int it = 0; it < 8; it++) {
            int fidx = it * 256 + tid;
            int rr = fidx >> 4, c4 = (fidx & 15) * 4;
            cpa16(xs_a + (rr * 68 + c4) * 4, xsrc + (size_t)rr * 512 + c4);
        }
        const float4* sp = g_w1p + ch * 2048;
        for (int i = tid; i < 2048; i += 256)
            cpa16(wp_a + i * 16, sp + i);
        CPA_COMMIT();
        CPA_WAIT0();
        __syncthreads();

#pragma unroll
        for (int ks = 0; ks < 8; ks++) {
            const int lc = ks * 8 + q;
            float a0f = xs[r0 * 68 + lc];
            float a1f = xs[r1 * 68 + lc];
            float a2f = xs[r0 * 68 + lc + 4];
            float a3f = xs[r1 * 68 + lc + 4];
            unsigned ahi[4], alo[4];
            ahi[0] = cvt_tf32(a0f); alo[0] = cvt_tf32(a0f - __uint_as_float(ahi[0]));
            ahi[1] = cvt_tf32(a1f); alo[1] = cvt_tf32(a1f - __uint_as_float(ahi[1]));
            ahi[2] = cvt_tf32(a2f); alo[2] = cvt_tf32(a2f - __uint_as_float(ahi[2]));
            ahi[3] = cvt_tf32(a3f); alo[3] = cvt_tf32(a3f - __uint_as_float(ahi[3]));

            const int base = ks * 256 + g * 4 + q;
#pragma unroll
            for (int j = 0; j < 8; j++) {
                float4 hl = wp[base + j * 32];
                unsigned hb0 = __float_as_uint(hl.x), hb1 = __float_as_uint(hl.y);
                unsigned lb0 = __float_as_uint(hl.z), lb1 = __float_as_uint(hl.w);
                mma1688t(d[j], ahi, hb0, hb1);
                mma1688t(d[j], ahi, lb0, lb1);
                mma1688t(d[j], alo, hb0, hb1);
            }
        }
    }

    float* o0 = &g_hin[(size_t)(blockRow + r0) * 64];
    float* o1 = &g_hin[(size_t)(blockRow + r1) * 64];
#pragma unroll
    for (int j = 0; j < 8; j++) {
        const float2 bb = *(const float2*)&b1[8 * j + 2 * q];
        float2 v0 = make_float2(d[j][0] + bb.x, d[j][1] + bb.y);
        float2 v1 = make_float2(d[j][2] + bb.x, d[j][3] + bb.y);
        *(float2*)&o0[8 * j + 2 * q] = v0;
        *(float2*)&o1[8 * j + 2 * q] = v1;
    }
}

// ---------------------------------------------------------------------------
// Kernel 2: LIF recurrence with nibble LUTs; warp handles 8 rows. (unchanged)
// ---------------------------------------------------------------------------
__global__ void __launch_bounds__(256) k2_recur(const float* __restrict__ W2,
                                                const float* __restrict__ b2,
                                                const float* __restrict__ W3,
                                                const float* __restrict__ b3) {
    __shared__ float  LUT2[16 * 16 * 16];
    __shared__ float2 LUT3p[4 * 16 * 32];

    const int tid = threadIdx.x;
    for (int e = tid; e < 4096; e += 256) {
        int np = e >> 8, nv = (e >> 4) & 15, i = e & 15;
        float s = 0.0f;
#pragma unroll
        for (int j = 0; j < 4; j++)
            if (nv & (1 << j)) s += W2[i * 64 + np * 4 + j];
        LUT2[e] = s;
    }
    for (int e = tid; e < 2048; e += 256) {
        int np = e >> 9, nv = (e >> 5) & 15, j = e & 31;
        float sx = 0.0f, sy = 0.0f;
#pragma unroll
        for (int jj = 0; jj < 4; jj++)
            if (nv & (1 << jj)) {
                sx += W3[j * 16 + np * 4 + jj];
                sy += W3[(j + 32) * 16 + np * 4 + jj];
            }
        LUT3p[e] = make_float2(sx, sy);
    }
    __syncthreads();

    const int warp = tid >> 5, lane = tid & 31;
    const int row0 = blockIdx.x * 64 + warp * 8;
    const int iL = lane & 15;
    const int half = lane >> 4;
    const float b2v = b2[iL];
    const float b3a = b3[lane];
    const float b3b = b3[lane + 32];

    float h0[8], h1[8], v1a[8], v1b[8], v2[8], v3a[8], v3b[8];
#pragma unroll
    for (int r = 0; r < 8; r++) {
        h0[r] = g_hin[(size_t)(row0 + r) * 64 + lane];
        h1[r] = g_hin[(size_t)(row0 + r) * 64 + 32 + lane];
        v1a[r] = v1b[r] = v2[r] = v3a[r] = v3b[r] = 0.0f;
    }

    for (int t = 0; t < 8; t++) {
        unsigned mlo[8], mhi[8];
#pragma unroll
        for (int r = 0; r < 8; r++) {
            v1a[r] += (h0[r] - v1a[r]) * 0.5f;
            bool s1a = v1a[r] >= 1.0f;
            if (s1a) v1a[r] = 0.0f;
            v1b[r] += (h1[r] - v1b[r]) * 0.5f;
            bool s1b = v1b[r] >= 1.0f;
            if (s1b) v1b[r] = 0.0f;
            mlo[r] = __ballot_sync(0xffffffffu, s1a);
            mhi[r] = __ballot_sync(0xffffffffu, s1b);
        }

#pragma unroll
        for (int r = 0; r < 8; r++) {
            unsigned w = half ? mhi[r] : mlo[r];
            float p2 = 0.0f;
#pragma unroll
            for (int p = 0; p < 8; p++) {
                unsigned nv = (w >> (4 * p)) & 15u;
                p2 += LUT2[(half * 8 + p) * 256 + nv * 16 + iL];
            }
            p2 += __shfl_xor_sync(0xffffffffu, p2, 16);
            float a2 = b2v + p2;
            v2[r] += (a2 - v2[r]) * 0.5f;
            bool s2 = v2[r] >= 1.0f;
            if (s2) v2[r] = 0.0f;
            unsigned m2 = __ballot_sync(0xffffffffu, s2) & 0xFFFFu;

            float i3a = b3a, i3b = b3b;
#pragma unroll
            for (int p = 0; p < 4; p++) {
                unsigned nv = (m2 >> (4 * p)) & 15u;
                float2 L = LUT3p[(p * 16 + nv) * 32 + lane];
                i3a += L.x;
                i3b += L.y;
            }
            v3a[r] += (i3a - v3a[r]) * 0.5f;
            bool s3a = v3a[r] >= 1.0f;
            if (s3a) v3a[r] = 0.0f;
            v3b[r] += (i3b - v3b[r]) * 0.5f;
            bool s3b = v3b[r] >= 1.0f;
            if (s3b) v3b[r] = 0.0f;

            unsigned olo = __ballot_sync(0xffffffffu, s3a);
            unsigned ohi = __ballot_sync(0xffffffffu, s3b);
            unsigned long long mo = ((unsigned long long)ohi << 32) | (unsigned long long)olo;
            if (lane == r) g_masks[(size_t)(row0 + r) * 8 + t] = mo;
        }
    }
}

// ---------------------------------------------------------------------------
// Kernel 3: fp16 HMMA, N = 8 batches, t accumulated in registers (no shfl).
// CTA = 32 b's x 128 cols. Producer: warp w makes frags for t=w (shared by
// all warps). Bias enters via MMA C operand; 0.5 tanh-scale folded into W4.
// ---------------------------------------------------------------------------
__global__ void __launch_bounds__(256) k3_mma(const float* __restrict__ b4,
                                              float* __restrict__ out) {
    __shared__ uint4 sf[4][8][32][2];   // [cc][t][lane][word01] = 32 KB

    const int tid = threadIdx.x;
    const int warp = tid >> 5, lane = tid & 31;
    const int g = lane >> 2;
    const int q = lane & 3;
    const int colbase = blockIdx.y * 128 + warp * 16;
    const int c0 = colbase + g;
    const int c1 = colbase + g + 8;
    const int bbase = blockIdx.x * 32;

    // A fragments (0.5*W4 fp16), register-resident
    unsigned af[4][4];
#pragma unroll
    for (int ks = 0; ks < 4; ks++) {
        af[ks][0] = g_w4f[c0 * 32 + ks * 8 + q];
        af[ks][1] = g_w4f[c1 * 32 + ks * 8 + q];
        af[ks][2] = g_w4f[c0 * 32 + ks * 8 + 4 + q];
        af[ks][3] = g_w4f[c1 * 32 + ks * 8 + 4 + q];
    }
    const float e0 = 0.5f * b4[c0];
    const float e1 = 0.5f * b4[c1];

    // Producer: this warp builds B-frags for t = warp, all 4 b-subchunks.
    // B-frag col n = g  ->  b = bbase + cc*8 + g.
#pragma unroll
    for (int cc = 0; cc < 4; cc++) {
        const unsigned long long m = g_masks[(size_t)(bbase + cc * 8 + g) * 8 + warp];
        unsigned wv[4][2];
#pragma unroll
        for (int ks = 0; ks < 4; ks++) {
            unsigned xx = (unsigned)(m >> (ks * 16 + 2 * q));
            unsigned s0 = (unsigned)((int)(xx << 31) >> 31) & 0x00003C00u;
            unsigned s1 = (unsigned)((int)(xx << 30) >> 31) & 0x3C000000u;
            wv[ks][0] = s0 | s1;
            unsigned yy = (unsigned)(m >> (ks * 16 + 8 + 2 * q));
            unsigned s2 = (unsigned)((int)(yy << 31) >> 31) & 0x00003C00u;
            unsigned s3 = (unsigned)((int)(yy << 30) >> 31) & 0x3C000000u;
            wv[ks][1] = s2 | s3;
        }
        sf[cc][warp][lane][0] = make_uint4(wv[0][0], wv[0][1], wv[1][0], wv[1][1]);
        sf[cc][warp][lane][1] = make_uint4(wv[2][0], wv[2][1], wv[3][0], wv[3][1]);
    }
    __syncthreads();

    // Consumer: D cols = b's (bbase + cc*8 + 2q, +2q+1); accumulate tanh over t.
#pragma unroll
    for (int cc = 0; cc < 4; cc++) {
        float accf[4] = {0.f, 0.f, 0.f, 0.f};
        unsigned prevA = 0, prevB = 0;
#pragma unroll
        for (int t = 0; t < 8; t++) {
            uint4 fa = sf[cc][t][lane][0];
            uint4 fb = sf[cc][t][lane][1];

            float d[4];
            mma16816h_c(d, af[0], fa.x, fa.y, e0, e0, e1, e1);
            mma16816h(d, af[1], fa.z, fa.w);
            mma16816h(d, af[2], fb.x, fb.y);
            mma16816h(d, af[3], fb.z, fb.w);

            __half2 hA = __floats2half2_rn(d[0], d[1]);
            __half2 hB = __floats2half2_rn(d[2], d[3]);
            unsigned tA = tanh2(*(unsigned*)&hA);
            unsigned tB = tanh2(*(unsigned*)&hB);
            if ((t & 1) == 0) {
                prevA = tA;
                prevB = tB;
            } else {
                __half2 sA = __hadd2(*(__half2*)&prevA, *(__half2*)&tA);
                __half2 sB = __hadd2(*(__half2*)&prevB, *(__half2*)&tB);
                float2 fA = __half22float2(sA);
                float2 fB = __half22float2(sB);
                accf[0] += fA.x; accf[1] += fA.y;
                accf[2] += fB.x; accf[3] += fB.y;
            }
        }
        const int b0 = bbase + cc * 8 + 2 * q;
        out[(size_t)b0 * 512 + c0]       = fmaf(accf[0], 0.0625f, 0.5f);
        out[(size_t)(b0 + 1) * 512 + c0] = fmaf(accf[1], 0.0625f, 0.5f);
        out[(size_t)b0 * 512 + c1]       = fmaf(accf[2], 0.0625f, 0.5f);
        out[(size_t)(b0 + 1) * 512 + c1] = fmaf(accf[3], 0.0625f, 0.5f);
    }
}

// ---------------------------------------------------------------------------
extern "C" void kernel_launch(void* const* d_in, const int* in_sizes, int n_in,
                              void* d_out, int out_size) {
    const float* x  = (const float*)d_in[0];
    const float* W1 = (const float*)d_in[1];
    const float* b1 = (const float*)d_in[2];
    const float* W2 = (const float*)d_in[3];
    const float* b2 = (const float*)d_in[4];
    const float* W3 = (const float*)d_in[5];
    const float* b3 = (const float*)d_in[6];
    const float* W4 = (const float*)d_in[7];
    const float* b4 = (const float*)d_in[8];
    float* out = (float*)d_out;

    static bool attr_set = false;
    if (!attr_set) {
        cudaFuncSetAttribute(k1_hin, cudaFuncAttributeMaxDynamicSharedMemorySize, 67584);
        attr_set = true;
    }

    k0_pack<<<128, 256>>>(W4, W1);
    k1_hin<<<B_TOTAL / 128, 256, 67584>>>(x, b1);
    k2_recur<<<B_TOTAL / 64, 256>>>(W2, b2, W3, b3);
    k3_mma<<<dim3(B_TOTAL / 32, 4), 256>>>(b4, out);
}

// round 8
// speedup vs baseline: 1.2048x; 1.2048x over previous
#include <cuda_runtime.h>
#include <cuda_fp16.h>
#include <cstdint>

// SNNAutoencoder: B=65536, D=512, H=64, L=16, T=8
// Inputs: x[65536,512], W1[64,512], b1[64], W2[16,64], b2[16],
//         W3[64,16], b3[64], W4[512,64], b4[512]    Output: float32 [65536,512]

#define B_TOTAL 65536

// Scratch (static device arrays)
__device__ float              g_hin[(size_t)B_TOTAL * 64];      // 16 MB
__device__ unsigned long long g_masks[(size_t)B_TOTAL * 8];     //  4 MB packed s3
__device__ unsigned           g_w4f[512 * 32];                  // fp16x2 (0.5*W4) [c][kpair]
__device__ float4             g_w1p[64 * 64 * 4];               // tf32 (hi0,hi4,lo0,lo4)

// ---------------------------------------------------------------------------
// helpers
// ---------------------------------------------------------------------------
__device__ __forceinline__ unsigned tanh2(unsigned h) {
    unsigned r;
    asm("tanh.approx.f16x2 %0, %1;" : "=r"(r) : "r"(h));
    return r;
}
__device__ __forceinline__ unsigned cvt_tf32(float f) {
    unsigned u;
    asm("cvt.rna.tf32.f32 %0, %1;" : "=r"(u) : "f"(f));
    return u;
}
__device__ __forceinline__ uint32_t smem_u32(const void* p) {
    uint32_t a;
    asm("{ .reg .u64 t; cvta.to.shared.u64 t, %1; cvt.u32.u64 %0, t; }" : "=r"(a) : "l"(p));
    return a;
}
__device__ __forceinline__ void cpa16(uint32_t dst, const void* src) {
    asm volatile("cp.async.ca.shared.global [%0], [%1], 16;" :: "r"(dst), "l"(src));
}
#define CPA_COMMIT() asm volatile("cp.async.commit_group;" ::: "memory")
#define CPA_WAIT0()  asm volatile("cp.async.wait_group 0;" ::: "memory")

// fp16 mma with explicit C operand (bias init): D = A*B + C
__device__ __forceinline__ void mma16816h_c(float* d, const unsigned* a,
                                            unsigned b0, unsigned b1,
                                            float c0, float c1, float c2, float c3) {
    asm volatile(
        "mma.sync.aligned.m16n8k16.row.col.f32.f16.f16.f32 "
        "{%0,%1,%2,%3}, {%4,%5,%6,%7}, {%8,%9}, {%10,%11,%12,%13};"
        : "=f"(d[0]), "=f"(d[1]), "=f"(d[2]), "=f"(d[3])
        : "r"(a[0]), "r"(a[1]), "r"(a[2]), "r"(a[3]), "r"(b0), "r"(b1),
          "f"(c0), "f"(c1), "f"(c2), "f"(c3));
}
__device__ __forceinline__ void mma16816h(float* d, const unsigned* a,
                                          unsigned b0, unsigned b1) {
    asm volatile(
        "mma.sync.aligned.m16n8k16.row.col.f32.f16.f16.f32 "
        "{%0,%1,%2,%3}, {%4,%5,%6,%7}, {%8,%9}, {%0,%1,%2,%3};"
        : "+f"(d[0]), "+f"(d[1]), "+f"(d[2]), "+f"(d[3])
        : "r"(a[0]), "r"(a[1]), "r"(a[2]), "r"(a[3]), "r"(b0), "r"(b1));
}
// tf32 mma
__device__ __forceinline__ void mma1688t(float* d, const unsigned* a,
                                         unsigned b0, unsigned b1) {
    asm volatile(
        "mma.sync.aligned.m16n8k8.row.col.f32.tf32.tf32.f32 "
        "{%0,%1,%2,%3}, {%4,%5,%6,%7}, {%8,%9}, {%0,%1,%2,%3};"
        : "+f"(d[0]), "+f"(d[1]), "+f"(d[2]), "+f"(d[3])
        : "r"(a[0]), "r"(a[1]), "r"(a[2]), "r"(a[3]), "r"(b0), "r"(b1));
}

// ---------------------------------------------------------------------------
// Kernel 0: pack 0.5*W4 (fp16x2) and W1 (tf32 hi/lo float4 interleaved)
// ---------------------------------------------------------------------------
__global__ void k0_pack(const float* __restrict__ W4,
                        const float* __restrict__ W1) {
    const int bid = blockIdx.x;
    const int idx = (bid & 63) * 256 + threadIdx.x;   // 0..16383
    if (bid < 64) {
        float w0 = 0.5f * W4[2 * idx], w1 = 0.5f * W4[2 * idx + 1];
        __half h0 = __float2half_rn(w0);
        __half h1 = __float2half_rn(w1);
        g_w4f[idx] = (unsigned)__half_as_ushort(h0) |
                     ((unsigned)__half_as_ushort(h1) << 16);
    } else {
        int ks = idx >> 8, n = (idx >> 2) & 63, q = idx & 3;
        float w0 = W1[n * 512 + ks * 8 + q];
        float w4 = W1[n * 512 + ks * 8 + q + 4];
        unsigned h0 = cvt_tf32(w0), h4 = cvt_tf32(w4);
        unsigned l0 = cvt_tf32(w0 - __uint_as_float(h0));
        unsigned l4 = cvt_tf32(w4 - __uint_as_float(h4));
        g_w1p[idx] = make_float4(__uint_as_float(h0), __uint_as_float(h4),
                                 __uint_as_float(l0), __uint_as_float(l4));
    }
}

// ---------------------------------------------------------------------------
// Kernel 1: h_in = x @ W1^T + b1 via 3xTF32 mma.sync (fp32-equivalent).
// ---------------------------------------------------------------------------
__global__ void __launch_bounds__(256) k1_hin(const float* __restrict__ x,
                                              const float* __restrict__ b1) {
    extern __shared__ float smemf[];
    float*  xs = smemf;                       // [128][68]  34816 B
    float4* wp = (float4*)(smemf + 8704);     // [2048]     32768 B

    const int tid = threadIdx.x;
    const int warp = tid >> 5, lane = tid & 31;
    const int g = lane >> 2, q = lane & 3;
    const int blockRow = blockIdx.x * 128;

    const uint32_t xs_a = smem_u32(xs);
    const uint32_t wp_a = smem_u32(wp);

    float d[8][4];
#pragma unroll
    for (int j = 0; j < 8; j++)
#pragma unroll
        for (int i = 0; i < 4; i++) d[j][i] = 0.0f;

    const int r0 = warp * 16 + g;
    const int r1 = r0 + 8;

    for (int ch = 0; ch < 8; ch++) {
        __syncthreads();
        const float* xsrc = x + (size_t)blockRow * 512 + ch * 64;
#pragma unroll
        for (int it = 0; it < 8; it++) {
            int fidx = it * 256 + tid;
            int rr = fidx >> 4, c4 = (fidx & 15) * 4;
            cpa16(xs_a + (rr * 68 + c4) * 4, xsrc + (size_t)rr * 512 + c4);
        }
        const float4* sp = g_w1p + ch * 2048;
        for (int i = tid; i < 2048; i += 256)
            cpa16(wp_a + i * 16, sp + i);
        CPA_COMMIT();
        CPA_WAIT0();
        __syncthreads();

#pragma unroll
        for (int ks = 0; ks < 8; ks++) {
            const int lc = ks * 8 + q;
            float a0f = xs[r0 * 68 + lc];
            float a1f = xs[r1 * 68 + lc];
            float a2f = xs[r0 * 68 + lc + 4];
            float a3f = xs[r1 * 68 + lc + 4];
            unsigned ahi[4], alo[4];
            ahi[0] = cvt_tf32(a0f); alo[0] = cvt_tf32(a0f - __uint_as_float(ahi[0]));
            ahi[1] = cvt_tf32(a1f); alo[1] = cvt_tf32(a1f - __uint_as_float(ahi[1]));
            ahi[2] = cvt_tf32(a2f); alo[2] = cvt_tf32(a2f - __uint_as_float(ahi[2]));
            ahi[3] = cvt_tf32(a3f); alo[3] = cvt_tf32(a3f - __uint_as_float(ahi[3]));

            const int base = ks * 256 + g * 4 + q;
#pragma unroll
            for (int j = 0; j < 8; j++) {
                float4 hl = wp[base + j * 32];
                unsigned hb0 = __float_as_uint(hl.x), hb1 = __float_as_uint(hl.y);
                unsigned lb0 = __float_as_uint(hl.z), lb1 = __float_as_uint(hl.w);
                mma1688t(d[j], ahi, hb0, hb1);
                mma1688t(d[j], ahi, lb0, lb1);
                mma1688t(d[j], alo, hb0, hb1);
            }
        }
    }

    float* o0 = &g_hin[(size_t)(blockRow + r0) * 64];
    float* o1 = &g_hin[(size_t)(blockRow + r1) * 64];
#pragma unroll
    for (int j = 0; j < 8; j++) {
        const float2 bb = *(const float2*)&b1[8 * j + 2 * q];
        float2 v0 = make_float2(d[j][0] + bb.x, d[j][1] + bb.y);
        float2 v1 = make_float2(d[j][2] + bb.x, d[j][3] + bb.y);
        *(float2*)&o0[8 * j + 2 * q] = v0;
        *(float2*)&o1[8 * j + 2 * q] = v1;
    }
}

// ---------------------------------------------------------------------------
// Kernel 2: LIF recurrence with nibble LUTs; warp handles 8 rows. (unchanged)
// ---------------------------------------------------------------------------
__global__ void __launch_bounds__(256) k2_recur(const float* __restrict__ W2,
                                                const float* __restrict__ b2,
                                                const float* __restrict__ W3,
                                                const float* __restrict__ b3) {
    __shared__ float  LUT2[16 * 16 * 16];
    __shared__ float2 LUT3p[4 * 16 * 32];

    const int tid = threadIdx.x;
    for (int e = tid; e < 4096; e += 256) {
        int np = e >> 8, nv = (e >> 4) & 15, i = e & 15;
        float s = 0.0f;
#pragma unroll
        for (int j = 0; j < 4; j++)
            if (nv & (1 << j)) s += W2[i * 64 + np * 4 + j];
        LUT2[e] = s;
    }
    for (int e = tid; e < 2048; e += 256) {
        int np = e >> 9, nv = (e >> 5) & 15, j = e & 31;
        float sx = 0.0f, sy = 0.0f;
#pragma unroll
        for (int jj = 0; jj < 4; jj++)
            if (nv & (1 << jj)) {
                sx += W3[j * 16 + np * 4 + jj];
                sy += W3[(j + 32) * 16 + np * 4 + jj];
            }
        LUT3p[e] = make_float2(sx, sy);
    }
    __syncthreads();

    const int warp = tid >> 5, lane = tid & 31;
    const int row0 = blockIdx.x * 64 + warp * 8;
    const int iL = lane & 15;
    const int half = lane >> 4;
    const float b2v = b2[iL];
    const float b3a = b3[lane];
    const float b3b = b3[lane + 32];

    float h0[8], h1[8], v1a[8], v1b[8], v2[8], v3a[8], v3b[8];
#pragma unroll
    for (int r = 0; r < 8; r++) {
        h0[r] = g_hin[(size_t)(row0 + r) * 64 + lane];
        h1[r] = g_hin[(size_t)(row0 + r) * 64 + 32 + lane];
        v1a[r] = v1b[r] = v2[r] = v3a[r] = v3b[r] = 0.0f;
    }

    for (int t = 0; t < 8; t++) {
        unsigned mlo[8], mhi[8];
#pragma unroll
        for (int r = 0; r < 8; r++) {
            v1a[r] += (h0[r] - v1a[r]) * 0.5f;
            bool s1a = v1a[r] >= 1.0f;
            if (s1a) v1a[r] = 0.0f;
            v1b[r] += (h1[r] - v1b[r]) * 0.5f;
            bool s1b = v1b[r] >= 1.0f;
            if (s1b) v1b[r] = 0.0f;
            mlo[r] = __ballot_sync(0xffffffffu, s1a);
            mhi[r] = __ballot_sync(0xffffffffu, s1b);
        }

#pragma unroll
        for (int r = 0; r < 8; r++) {
            unsigned w = half ? mhi[r] : mlo[r];
            float p2 = 0.0f;
#pragma unroll
            for (int p = 0; p < 8; p++) {
                unsigned nv = (w >> (4 * p)) & 15u;
                p2 += LUT2[(half * 8 + p) * 256 + nv * 16 + iL];
            }
            p2 += __shfl_xor_sync(0xffffffffu, p2, 16);
            float a2 = b2v + p2;
            v2[r] += (a2 - v2[r]) * 0.5f;
            bool s2 = v2[r] >= 1.0f;
            if (s2) v2[r] = 0.0f;
            unsigned m2 = __ballot_sync(0xffffffffu, s2) & 0xFFFFu;

            float i3a = b3a, i3b = b3b;
#pragma unroll
            for (int p = 0; p < 4; p++) {
                unsigned nv = (m2 >> (4 * p)) & 15u;
                float2 L = LUT3p[(p * 16 + nv) * 32 + lane];
                i3a += L.x;
                i3b += L.y;
            }
            v3a[r] += (i3a - v3a[r]) * 0.5f;
            bool s3a = v3a[r] >= 1.0f;
            if (s3a) v3a[r] = 0.0f;
            v3b[r] += (i3b - v3b[r]) * 0.5f;
            bool s3b = v3b[r] >= 1.0f;
            if (s3b) v3b[r] = 0.0f;

            unsigned olo = __ballot_sync(0xffffffffu, s3a);
            unsigned ohi = __ballot_sync(0xffffffffu, s3b);
            unsigned long long mo = ((unsigned long long)ohi << 32) | (unsigned long long)olo;
            if (lane == r) g_masks[(size_t)(row0 + r) * 8 + t] = mo;
        }
    }
}

// ---------------------------------------------------------------------------
// Kernel 3: fp16 HMMA, N = 8 batches, t accumulated in registers (no shfl).
// Frag buffers split (lane-innermost, 16B stride) -> conflict-free LDS/STS.
// CTA covers 128 b x 128 cols via 4 groups of 32 b.
// ---------------------------------------------------------------------------
__global__ void __launch_bounds__(256) k3_mma(const float* __restrict__ b4,
                                              float* __restrict__ out) {
    __shared__ uint4 sf0[8][4][32];   // [t][cc][lane] frag ks0/ks1, 16 KB
    __shared__ uint4 sf1[8][4][32];   // [t][cc][lane] frag ks2/ks3, 16 KB

    const int tid = threadIdx.x;
    const int warp = tid >> 5, lane = tid & 31;
    const int g = lane >> 2;
    const int q = lane & 3;
    const int colbase = blockIdx.y * 128 + warp * 16;
    const int c0 = colbase + g;
    const int c1 = colbase + g + 8;

    // A fragments (0.5*W4 fp16), register-resident for all 4 groups
    unsigned af[4][4];
#pragma unroll
    for (int ks = 0; ks < 4; ks++) {
        af[ks][0] = g_w4f[c0 * 32 + ks * 8 + q];
        af[ks][1] = g_w4f[c1 * 32 + ks * 8 + q];
        af[ks][2] = g_w4f[c0 * 32 + ks * 8 + 4 + q];
        af[ks][3] = g_w4f[c1 * 32 + ks * 8 + 4 + q];
    }
    const float e0 = 0.5f * b4[c0];
    const float e1 = 0.5f * b4[c1];

    for (int it = 0; it < 4; it++) {
        const int bbase = blockIdx.x * 128 + it * 32;

        // Producer: warp w builds frags for t = w; B-frag col n = g -> b index.
#pragma unroll
        for (int cc = 0; cc < 4; cc++) {
            const unsigned long long m = g_masks[(size_t)(bbase + cc * 8 + g) * 8 + warp];
            unsigned wv[4][2];
#pragma unroll
            for (int ks = 0; ks < 4; ks++) {
                unsigned xx = (unsigned)(m >> (ks * 16 + 2 * q));
                unsigned s0 = (unsigned)((int)(xx << 31) >> 31) & 0x00003C00u;
                unsigned s1 = (unsigned)((int)(xx << 30) >> 31) & 0x3C000000u;
                wv[ks][0] = s0 | s1;
                unsigned yy = (unsigned)(m >> (ks * 16 + 8 + 2 * q));
                unsigned s2 = (unsigned)((int)(yy << 31) >> 31) & 0x00003C00u;
                unsigned s3 = (unsigned)((int)(yy << 30) >> 31) & 0x3C000000u;
                wv[ks][1] = s2 | s3;
            }
            sf0[warp][cc][lane] = make_uint4(wv[0][0], wv[0][1], wv[1][0], wv[1][1]);
            sf1[warp][cc][lane] = make_uint4(wv[2][0], wv[2][1], wv[3][0], wv[3][1]);
        }
        __syncthreads();

        // Consumer: D cols = b's; accumulate tanh over t in registers.
#pragma unroll
        for (int cc = 0; cc < 4; cc++) {
            float accf[4] = {0.f, 0.f, 0.f, 0.f};
            unsigned prevA = 0, prevB = 0;
#pragma unroll
            for (int t = 0; t < 8; t++) {
                uint4 fa = sf0[t][cc][lane];
                uint4 fb = sf1[t][cc][lane];

                float d[4];
                mma16816h_c(d, af[0], fa.x, fa.y, e0, e0, e1, e1);
                mma16816h(d, af[1], fa.z, fa.w);
                mma16816h(d, af[2], fb.x, fb.y);
                mma16816h(d, af[3], fb.z, fb.w);

                __half2 hA = __floats2half2_rn(d[0], d[1]);
                __half2 hB = __floats2half2_rn(d[2], d[3]);
                unsigned tA = tanh2(*(unsigned*)&hA);
                unsigned tB = tanh2(*(unsigned*)&hB);
                if ((t & 1) == 0) {
                    prevA = tA;
                    prevB = tB;
                } else {
                    __half2 sA = __hadd2(*(__half2*)&prevA, *(__half2*)&tA);
                    __half2 sB = __hadd2(*(__half2*)&prevB, *(__half2*)&tB);
                    float2 fA = __half22float2(sA);
                    float2 fB = __half22float2(sB);
                    accf[0] += fA.x; accf[1] += fA.y;
                    accf[2] += fB.x; accf[3] += fB.y;
                }
            }
            const int b0 = bbase + cc * 8 + 2 * q;
            out[(size_t)b0 * 512 + c0]       = fmaf(accf[0], 0.0625f, 0.5f);
            out[(size_t)(b0 + 1) * 512 + c0] = fmaf(accf[1], 0.0625f, 0.5f);
            out[(size_t)b0 * 512 + c1]       = fmaf(accf[2], 0.0625f, 0.5f);
            out[(size_t)(b0 + 1) * 512 + c1] = fmaf(accf[3], 0.0625f, 0.5f);
        }
        __syncthreads();
    }
}

// ---------------------------------------------------------------------------
extern "C" void kernel_launch(void* const* d_in, const int* in_sizes, int n_in,
                              void* d_out, int out_size) {
    const float* x  = (const float*)d_in[0];
    const float* W1 = (const float*)d_in[1];
    const float* b1 = (const float*)d_in[2];
    const float* W2 = (const float*)d_in[3];
    const float* b2 = (const float*)d_in[4];
    const float* W3 = (const float*)d_in[5];
    const float* b3 = (const float*)d_in[6];
    const float* W4 = (const float*)d_in[7];
    const float* b4 = (const float*)d_in[8];
    float* out = (float*)d_out;

    static bool attr_set = false;
    if (!attr_set) {
        cudaFuncSetAttribute(k1_hin, cudaFuncAttributeMaxDynamicSharedMemorySize, 67584);
        attr_set = true;
    }

    k0_pack<<<128, 256>>>(W4, W1);
    k1_hin<<<B_TOTAL / 128, 256, 67584>>>(x, b1);
    k2_recur<<<B_TOTAL / 64, 256>>>(W2, b2, W3, b3);
    k3_mma<<<dim3(B_TOTAL / 128, 4), 256>>>(b4, out);
}

// round 9
// speedup vs baseline: 1.3036x; 1.0819x over previous
#include <cuda_runtime.h>
#include <cuda_fp16.h>
#include <cstdint>

// SNNAutoencoder: B=65536, D=512, H=64, L=16, T=8
// Inputs: x[65536,512], W1[64,512], b1[64], W2[16,64], b2[16],
//         W3[64,16], b3[64], W4[512,64], b4[512]    Output: float32 [65536,512]

#define B_TOTAL 65536

// Scratch (static device arrays)
__device__ float              g_hin[(size_t)B_TOTAL * 64];      // 16 MB
__device__ unsigned long long g_masks[(size_t)B_TOTAL * 8];     //  4 MB packed s3
__device__ unsigned           g_w4f[512 * 32];                  // fp16x2 (0.5*W4) [c][kpair]
__device__ uint4              g_w1h[32 * 8 * 32];               // fp16 hi/lo B-frags [ks][j][lane]

// ---------------------------------------------------------------------------
// helpers
// ---------------------------------------------------------------------------
__device__ __forceinline__ unsigned tanh2(unsigned h) {
    unsigned r;
    asm("tanh.approx.f16x2 %0, %1;" : "=r"(r) : "r"(h));
    return r;
}
__device__ __forceinline__ uint32_t smem_u32(const void* p) {
    uint32_t a;
    asm("{ .reg .u64 t; cvta.to.shared.u64 t, %1; cvt.u32.u64 %0, t; }" : "=r"(a) : "l"(p));
    return a;
}
__device__ __forceinline__ void cpa16(uint32_t dst, const void* src) {
    asm volatile("cp.async.ca.shared.global [%0], [%1], 16;" :: "r"(dst), "l"(src));
}
#define CPA_COMMIT() asm volatile("cp.async.commit_group;" ::: "memory")
#define CPA_WAIT0()  asm volatile("cp.async.wait_group 0;" ::: "memory")

// fp16 mma with explicit C operand (bias init): D = A*B + C
__device__ __forceinline__ void mma16816h_c(float* d, const unsigned* a,
                                            unsigned b0, unsigned b1,
                                            float c0, float c1, float c2, float c3) {
    asm volatile(
        "mma.sync.aligned.m16n8k16.row.col.f32.f16.f16.f32 "
        "{%0,%1,%2,%3}, {%4,%5,%6,%7}, {%8,%9}, {%10,%11,%12,%13};"
        : "=f"(d[0]), "=f"(d[1]), "=f"(d[2]), "=f"(d[3])
        : "r"(a[0]), "r"(a[1]), "r"(a[2]), "r"(a[3]), "r"(b0), "r"(b1),
          "f"(c0), "f"(c1), "f"(c2), "f"(c3));
}
__device__ __forceinline__ void mma16816h(float* d, const unsigned* a,
                                          unsigned b0, unsigned b1) {
    asm volatile(
        "mma.sync.aligned.m16n8k16.row.col.f32.f16.f16.f32 "
        "{%0,%1,%2,%3}, {%4,%5,%6,%7}, {%8,%9}, {%0,%1,%2,%3};"
        : "+f"(d[0]), "+f"(d[1]), "+f"(d[2]), "+f"(d[3])
        : "r"(a[0]), "r"(a[1]), "r"(a[2]), "r"(a[3]), "r"(b0), "r"(b1));
}

// split float2 -> fp16x2 hi + lo (exact residual)
__device__ __forceinline__ unsigned split_hl(float2 f, unsigned& lo) {
    __half2 h = __floats2half2_rn(f.x, f.y);
    float2 hf = __half22float2(h);
    __half2 l = __floats2half2_rn(f.x - hf.x, f.y - hf.y);
    lo = *(unsigned*)&l;
    return *(unsigned*)&h;
}

// ---------------------------------------------------------------------------
// Kernel 0: pack 0.5*W4 (fp16x2) and W1 (fp16 hi/lo B-fragments)
// ---------------------------------------------------------------------------
__global__ void k0_pack(const float* __restrict__ W4,
                        const float* __restrict__ W1) {
    const int bid = blockIdx.x;
    if (bid < 64) {
        const int idx = bid * 256 + threadIdx.x;   // 0..16383
        float w0 = 0.5f * W4[2 * idx], w1 = 0.5f * W4[2 * idx + 1];
        __half h0 = __float2half_rn(w0);
        __half h1 = __float2half_rn(w1);
        g_w4f[idx] = (unsigned)__half_as_ushort(h0) |
                     ((unsigned)__half_as_ushort(h1) << 16);
    } else {
        const int idx = (bid - 64) * 256 + threadIdx.x;   // 0..8191
        int ks = idx >> 8, j = (idx >> 5) & 7, lane = idx & 31;
        int g = lane >> 2, q = lane & 3;
        int n = 8 * j + g;
        const float* src = W1 + n * 512 + ks * 16;
        float2 f0 = make_float2(src[2 * q], src[2 * q + 1]);
        float2 f1 = make_float2(src[8 + 2 * q], src[8 + 2 * q + 1]);
        unsigned lo0, lo1;
        unsigned hi0 = split_hl(f0, lo0);
        unsigned hi1 = split_hl(f1, lo1);
        g_w1h[idx] = make_uint4(hi0, hi1, lo0, lo1);
    }
}

// ---------------------------------------------------------------------------
// Kernel 1: h_in = x @ W1^T + b1 via 3x fp16 mma.sync (hi/lo split,
// fp32-equivalent for these ranges). x staged via cp.async.
// ---------------------------------------------------------------------------
__global__ void __launch_bounds__(256) k1_hin(const float* __restrict__ x,
                                              const float* __restrict__ b1) {
    extern __shared__ float smemf[];
    float* xs = smemf;                         // [128][68]  34816 B
    uint4* wf = (uint4*)(smemf + 8704);        // [1024]     16384 B

    const int tid = threadIdx.x;
    const int warp = tid >> 5, lane = tid & 31;
    const int g = lane >> 2, q = lane & 3;
    const int blockRow = blockIdx.x * 128;

    const uint32_t xs_a = smem_u32(xs);
    const uint32_t wf_a = smem_u32(wf);

    float d[8][4];
#pragma unroll
    for (int j = 0; j < 8; j++)
#pragma unroll
        for (int i = 0; i < 4; i++) d[j][i] = 0.0f;

    const int r0 = warp * 16 + g;
    const int r1 = r0 + 8;

    for (int ch = 0; ch < 8; ch++) {
        __syncthreads();
        const float* xsrc = x + (size_t)blockRow * 512 + ch * 64;
#pragma unroll
        for (int it = 0; it < 8; it++) {
            int fidx = it * 256 + tid;
            int rr = fidx >> 4, c4 = (fidx & 15) * 4;
            cpa16(xs_a + (rr * 68 + c4) * 4, xsrc + (size_t)rr * 512 + c4);
        }
        const uint4* sp = g_w1h + ch * 1024;
#pragma unroll
        for (int i = 0; i < 4; i++)
            cpa16(wf_a + (i * 256 + tid) * 16, sp + i * 256 + tid);
        CPA_COMMIT();
        CPA_WAIT0();
        __syncthreads();

#pragma unroll
        for (int ks = 0; ks < 4; ks++) {
            const int lc = ks * 16 + 2 * q;
            float2 f00 = *(const float2*)&xs[r0 * 68 + lc];
            float2 f10 = *(const float2*)&xs[r1 * 68 + lc];
            float2 f08 = *(const float2*)&xs[r0 * 68 + lc + 8];
            float2 f18 = *(const float2*)&xs[r1 * 68 + lc + 8];
            unsigned ahi[4], alo[4];
            ahi[0] = split_hl(f00, alo[0]);
            ahi[1] = split_hl(f10, alo[1]);
            ahi[2] = split_hl(f08, alo[2]);
            ahi[3] = split_hl(f18, alo[3]);

            const int base = ks * 256 + lane;
#pragma unroll
            for (int j = 0; j < 8; j++) {
                uint4 w = wf[base + j * 32];
                mma16816h(d[j], ahi, w.x, w.y);   // hi * hi
                mma16816h(d[j], ahi, w.z, w.w);   // hi * lo
                mma16816h(d[j], alo, w.x, w.y);   // lo * hi
            }
        }
    }

    float* o0 = &g_hin[(size_t)(blockRow + r0) * 64];
    float* o1 = &g_hin[(size_t)(blockRow + r1) * 64];
#pragma unroll
    for (int j = 0; j < 8; j++) {
        const float2 bb = *(const float2*)&b1[8 * j + 2 * q];
        float2 v0 = make_float2(d[j][0] + bb.x, d[j][1] + bb.y);
        float2 v1 = make_float2(d[j][2] + bb.x, d[j][3] + bb.y);
        *(float2*)&o0[8 * j + 2 * q] = v0;
        *(float2*)&o1[8 * j + 2 * q] = v1;
    }
}

// ---------------------------------------------------------------------------
// Kernel 2: LIF recurrence with nibble LUTs; warp handles 8 rows. (unchanged)
// ---------------------------------------------------------------------------
__global__ void __launch_bounds__(256) k2_recur(const float* __restrict__ W2,
                                                const float* __restrict__ b2,
                                                const float* __restrict__ W3,
                                                const float* __restrict__ b3) {
    __shared__ float  LUT2[16 * 16 * 16];
    __shared__ float2 LUT3p[4 * 16 * 32];

    const int tid = threadIdx.x;
    for (int e = tid; e < 4096; e += 256) {
        int np = e >> 8, nv = (e >> 4) & 15, i = e & 15;
        float s = 0.0f;
#pragma unroll
        for (int j = 0; j < 4; j++)
            if (nv & (1 << j)) s += W2[i * 64 + np * 4 + j];
        LUT2[e] = s;
    }
    for (int e = tid; e < 2048; e += 256) {
        int np = e >> 9, nv = (e >> 5) & 15, j = e & 31;
        float sx = 0.0f, sy = 0.0f;
#pragma unroll
        for (int jj = 0; jj < 4; jj++)
            if (nv & (1 << jj)) {
                sx += W3[j * 16 + np * 4 + jj];
                sy += W3[(j + 32) * 16 + np * 4 + jj];
            }
        LUT3p[e] = make_float2(sx, sy);
    }
    __syncthreads();

    const int warp = tid >> 5, lane = tid & 31;
    const int row0 = blockIdx.x * 64 + warp * 8;
    const int iL = lane & 15;
    const int half = lane >> 4;
    const float b2v = b2[iL];
    const float b3a = b3[lane];
    const float b3b = b3[lane + 32];

    float h0[8], h1[8], v1a[8], v1b[8], v2[8], v3a[8], v3b[8];
#pragma unroll
    for (int r = 0; r < 8; r++) {
        h0[r] = g_hin[(size_t)(row0 + r) * 64 + lane];
        h1[r] = g_hin[(size_t)(row0 + r) * 64 + 32 + lane];
        v1a[r] = v1b[r] = v2[r] = v3a[r] = v3b[r] = 0.0f;
    }

    for (int t = 0; t < 8; t++) {
        unsigned mlo[8], mhi[8];
#pragma unroll
        for (int r = 0; r < 8; r++) {
            v1a[r] += (h0[r] - v1a[r]) * 0.5f;
            bool s1a = v1a[r] >= 1.0f;
            if (s1a) v1a[r] = 0.0f;
            v1b[r] += (h1[r] - v1b[r]) * 0.5f;
            bool s1b = v1b[r] >= 1.0f;
            if (s1b) v1b[r] = 0.0f;
            mlo[r] = __ballot_sync(0xffffffffu, s1a);
            mhi[r] = __ballot_sync(0xffffffffu, s1b);
        }

#pragma unroll
        for (int r = 0; r < 8; r++) {
            unsigned w = half ? mhi[r] : mlo[r];
            float p2 = 0.0f;
#pragma unroll
            for (int p = 0; p < 8; p++) {
                unsigned nv = (w >> (4 * p)) & 15u;
                p2 += LUT2[(half * 8 + p) * 256 + nv * 16 + iL];
            }
            p2 += __shfl_xor_sync(0xffffffffu, p2, 16);
            float a2 = b2v + p2;
            v2[r] += (a2 - v2[r]) * 0.5f;
            bool s2 = v2[r] >= 1.0f;
            if (s2) v2[r] = 0.0f;
            unsigned m2 = __ballot_sync(0xffffffffu, s2) & 0xFFFFu;

            float i3a = b3a, i3b = b3b;
#pragma unroll
            for (int p = 0; p < 4; p++) {
                unsigned nv = (m2 >> (4 * p)) & 15u;
                float2 L = LUT3p[(p * 16 + nv) * 32 + lane];
                i3a += L.x;
                i3b += L.y;
            }
            v3a[r] += (i3a - v3a[r]) * 0.5f;
            bool s3a = v3a[r] >= 1.0f;
            if (s3a) v3a[r] = 0.0f;
            v3b[r] += (i3b - v3b[r]) * 0.5f;
            bool s3b = v3b[r] >= 1.0f;
            if (s3b) v3b[r] = 0.0f;

            unsigned olo = __ballot_sync(0xffffffffu, s3a);
            unsigned ohi = __ballot_sync(0xffffffffu, s3b);
            unsigned long long mo = ((unsigned long long)ohi << 32) | (unsigned long long)olo;
            if (lane == r) g_masks[(size_t)(row0 + r) * 8 + t] = mo;
        }
    }
}

// ---------------------------------------------------------------------------
// Kernel 3: fp16 HMMA, N = 8 batches, t accumulated in registers.
// Stores staged through padded smem buffer -> coalesced float4 STG.
// ---------------------------------------------------------------------------
#define K3_SMEM (16384 + 16384 + 32 * 132 * 4)

__global__ void __launch_bounds__(256) k3_mma(const float* __restrict__ b4,
                                              float* __restrict__ out) {
    extern __shared__ char k3s[];
    uint4 (*sf0)[4][32] = (uint4(*)[4][32])k3s;              // [8][4][32] 16 KB
    uint4 (*sf1)[4][32] = (uint4(*)[4][32])(k3s + 16384);    // 16 KB
    float* obuf = (float*)(k3s + 32768);                     // [32][132] 16896 B

    const int tid = threadIdx.x;
    const int warp = tid >> 5, lane = tid & 31;
    const int g = lane >> 2;
    const int q = lane & 3;
    const int colbase = blockIdx.y * 128 + warp * 16;
    const int c0 = colbase + g;
    const int c1 = colbase + g + 8;

    unsigned af[4][4];
#pragma unroll
    for (int ks = 0; ks < 4; ks++) {
        af[ks][0] = g_w4f[c0 * 32 + ks * 8 + q];
        af[ks][1] = g_w4f[c1 * 32 + ks * 8 + q];
        af[ks][2] = g_w4f[c0 * 32 + ks * 8 + 4 + q];
        af[ks][3] = g_w4f[c1 * 32 + ks * 8 + 4 + q];
    }
    const float e0 = 0.5f * b4[c0];
    const float e1 = 0.5f * b4[c1];

    for (int it = 0; it < 4; it++) {
        const int bbase = blockIdx.x * 128 + it * 32;

        // Producer: warp w builds frags for t = w.
#pragma unroll
        for (int cc = 0; cc < 4; cc++) {
            const unsigned long long m = g_masks[(size_t)(bbase + cc * 8 + g) * 8 + warp];
            unsigned wv[4][2];
#pragma unroll
            for (int ks = 0; ks < 4; ks++) {
                unsigned xx = (unsigned)(m >> (ks * 16 + 2 * q));
                unsigned s0 = (unsigned)((int)(xx << 31) >> 31) & 0x00003C00u;
                unsigned s1 = (unsigned)((int)(xx << 30) >> 31) & 0x3C000000u;
                wv[ks][0] = s0 | s1;
                unsigned yy = (unsigned)(m >> (ks * 16 + 8 + 2 * q));
                unsigned s2 = (unsigned)((int)(yy << 31) >> 31) & 0x00003C00u;
                unsigned s3 = (unsigned)((int)(yy << 30) >> 31) & 0x3C000000u;
                wv[ks][1] = s2 | s3;
            }
            sf0[warp][cc][lane] = make_uint4(wv[0][0], wv[0][1], wv[1][0], wv[1][1]);
            sf1[warp][cc][lane] = make_uint4(wv[2][0], wv[2][1], wv[3][0], wv[3][1]);
        }
        __syncthreads();

        // Consumer: accumulate tanh over t; write results to obuf (conflict-free).
#pragma unroll
        for (int cc = 0; cc < 4; cc++) {
            float accf[4] = {0.f, 0.f, 0.f, 0.f};
            unsigned prevA = 0, prevB = 0;
#pragma unroll
            for (int t = 0; t < 8; t++) {
                uint4 fa = sf0[t][cc][lane];
                uint4 fb = sf1[t][cc][lane];

                float d[4];
                mma16816h_c(d, af[0], fa.x, fa.y, e0, e0, e1, e1);
                mma16816h(d, af[1], fa.z, fa.w);
                mma16816h(d, af[2], fb.x, fb.y);
                mma16816h(d, af[3], fb.z, fb.w);

                __half2 hA = __floats2half2_rn(d[0], d[1]);
                __half2 hB = __floats2half2_rn(d[2], d[3]);
                unsigned tA = tanh2(*(unsigned*)&hA);
                unsigned tB = tanh2(*(unsigned*)&hB);
                if ((t & 1) == 0) {
                    prevA = tA;
                    prevB = tB;
                } else {
                    __half2 sA = __hadd2(*(__half2*)&prevA, *(__half2*)&tA);
                    __half2 sB = __hadd2(*(__half2*)&prevB, *(__half2*)&tB);
                    float2 fA = __half22float2(sA);
                    float2 fB = __half22float2(sB);
                    accf[0] += fA.x; accf[1] += fA.y;
                    accf[2] += fB.x; accf[3] += fB.y;
                }
            }
            const int bl = cc * 8 + 2 * q;
            const int cL0 = warp * 16 + g;
            obuf[bl * 132 + cL0]           = fmaf(accf[0], 0.0625f, 0.5f);
            obuf[(bl + 1) * 132 + cL0]     = fmaf(accf[1], 0.0625f, 0.5f);
            obuf[bl * 132 + cL0 + 8]       = fmaf(accf[2], 0.0625f, 0.5f);
            obuf[(bl + 1) * 132 + cL0 + 8] = fmaf(accf[3], 0.0625f, 0.5f);
        }
        __syncthreads();

        // Coalesced store: 32 rows x 128 cols, float4 per thread x4.
        float* odst = out + (size_t)bbase * 512 + blockIdx.y * 128;
#pragma unroll
        for (int k = 0; k < 4; k++) {
            int idx = k * 256 + tid;
            int bl = idx >> 5, c4 = (idx & 31) * 4;
            float4 v = *(float4*)&obuf[bl * 132 + c4];
            *(float4*)(odst + (size_t)bl * 512 + c4) = v;
        }
        __syncthreads();
    }
}

// ---------------------------------------------------------------------------
extern "C" void kernel_launch(void* const* d_in, const int* in_sizes, int n_in,
                              void* d_out, int out_size) {
    const float* x  = (const float*)d_in[0];
    const float* W1 = (const float*)d_in[1];
    const float* b1 = (const float*)d_in[2];
    const float* W2 = (const float*)d_in[3];
    const float* b2 = (const float*)d_in[4];
    const float* W3 = (const float*)d_in[5];
    const float* b3 = (const float*)d_in[6];
    const float* W4 = (const float*)d_in[7];
    const float* b4 = (const float*)d_in[8];
    float* out = (float*)d_out;

    static bool attr_set = false;
    if (!attr_set) {
        cudaFuncSetAttribute(k1_hin, cudaFuncAttributeMaxDynamicSharedMemorySize, 51200);
        cudaFuncSetAttribute(k3_mma, cudaFuncAttributeMaxDynamicSharedMemorySize, K3_SMEM);
        attr_set = true;
    }

    k0_pack<<<96, 256>>>(W4, W1);
    k1_hin<<<B_TOTAL / 128, 256, 51200>>>(x, b1);
    k2_recur<<<B_TOTAL / 64, 256>>>(W2, b2, W3, b3);
    k3_mma<<<dim3(B_TOTAL / 128, 4), 256, K3_SMEM>>>(b4, out);
}

// round 10
// speedup vs baseline: 1.4023x; 1.0757x over previous
#include <cuda_runtime.h>
#include <cuda_fp16.h>
#include <cstdint>

// SNNAutoencoder: B=65536, D=512, H=64, L=16, T=8
// Inputs: x[65536,512], W1[64,512], b1[64], W2[16,64], b2[16],
//         W3[64,16], b3[64], W4[512,64], b4[512]    Output: float32 [65536,512]

#define B_TOTAL 65536

// Scratch (static device arrays)
__device__ float              g_hin[(size_t)B_TOTAL * 64];      // 16 MB
__device__ unsigned long long g_masks[(size_t)B_TOTAL * 8];     //  4 MB packed s3
__device__ unsigned           g_w4f[512 * 32];                  // fp16x2 (0.5*W4) [c][kpair]
__device__ uint4              g_w1h[32 * 8 * 32];               // fp16 hi/lo B-frags [ks][j][lane]

// ---------------------------------------------------------------------------
// helpers
// ---------------------------------------------------------------------------
__device__ __forceinline__ unsigned tanh2(unsigned h) {
    unsigned r;
    asm("tanh.approx.f16x2 %0, %1;" : "=r"(r) : "r"(h));
    return r;
}
__device__ __forceinline__ uint32_t smem_u32(const void* p) {
    uint32_t a;
    asm("{ .reg .u64 t; cvta.to.shared.u64 t, %1; cvt.u32.u64 %0, t; }" : "=r"(a) : "l"(p));
    return a;
}
__device__ __forceinline__ void cpa16(uint32_t dst, const void* src) {
    asm volatile("cp.async.ca.shared.global [%0], [%1], 16;" :: "r"(dst), "l"(src));
}
#define CPA_COMMIT() asm volatile("cp.async.commit_group;" ::: "memory")
#define CPA_WAIT0()  asm volatile("cp.async.wait_group 0;" ::: "memory")

// fp16 mma, f32 accum (k1)
__device__ __forceinline__ void mma16816h(float* d, const unsigned* a,
                                          unsigned b0, unsigned b1) {
    asm volatile(
        "mma.sync.aligned.m16n8k16.row.col.f32.f16.f16.f32 "
        "{%0,%1,%2,%3}, {%4,%5,%6,%7}, {%8,%9}, {%0,%1,%2,%3};"
        : "+f"(d[0]), "+f"(d[1]), "+f"(d[2]), "+f"(d[3])
        : "r"(a[0]), "r"(a[1]), "r"(a[2]), "r"(a[3]), "r"(b0), "r"(b1));
}
// fp16 mma, f16 accum (k3): D,C = 2 regs (half2 each)
__device__ __forceinline__ void mma16816hh(unsigned* d, const unsigned* a,
                                           unsigned b0, unsigned b1) {
    asm volatile(
        "mma.sync.aligned.m16n8k16.row.col.f16.f16.f16.f16 "
        "{%0,%1}, {%2,%3,%4,%5}, {%6,%7}, {%0,%1};"
        : "+r"(d[0]), "+r"(d[1])
        : "r"(a[0]), "r"(a[1]), "r"(a[2]), "r"(a[3]), "r"(b0), "r"(b1));
}

// split float2 -> fp16x2 hi + lo (exact residual)
__device__ __forceinline__ unsigned split_hl(float2 f, unsigned& lo) {
    __half2 h = __floats2half2_rn(f.x, f.y);
    float2 hf = __half22float2(h);
    __half2 l = __floats2half2_rn(f.x - hf.x, f.y - hf.y);
    lo = *(unsigned*)&l;
    return *(unsigned*)&h;
}

// ---------------------------------------------------------------------------
// Kernel 0: pack 0.5*W4 (fp16x2) and W1 (fp16 hi/lo B-fragments)
// ---------------------------------------------------------------------------
__global__ void k0_pack(const float* __restrict__ W4,
                        const float* __restrict__ W1) {
    const int bid = blockIdx.x;
    if (bid < 64) {
        const int idx = bid * 256 + threadIdx.x;   // 0..16383
        float w0 = 0.5f * W4[2 * idx], w1 = 0.5f * W4[2 * idx + 1];
        __half h0 = __float2half_rn(w0);
        __half h1 = __float2half_rn(w1);
        g_w4f[idx] = (unsigned)__half_as_ushort(h0) |
                     ((unsigned)__half_as_ushort(h1) << 16);
    } else {
        const int idx = (bid - 64) * 256 + threadIdx.x;   // 0..8191
        int ks = idx >> 8, j = (idx >> 5) & 7, lane = idx & 31;
        int g = lane >> 2, q = lane & 3;
        int n = 8 * j + g;
        const float* src = W1 + n * 512 + ks * 16;
        float2 f0 = make_float2(src[2 * q], src[2 * q + 1]);
        float2 f1 = make_float2(src[8 + 2 * q], src[8 + 2 * q + 1]);
        unsigned lo0, lo1;
        unsigned hi0 = split_hl(f0, lo0);
        unsigned hi1 = split_hl(f1, lo1);
        g_w1h[idx] = make_uint4(hi0, hi1, lo0, lo1);
    }
}

// ---------------------------------------------------------------------------
// Kernel 1: h_in = x @ W1^T + b1 via 3x fp16 mma.sync (hi/lo split).
// ---------------------------------------------------------------------------
__global__ void __launch_bounds__(256) k1_hin(const float* __restrict__ x,
                                              const float* __restrict__ b1) {
    extern __shared__ float smemf[];
    float* xs = smemf;                         // [128][68]  34816 B
    uint4* wf = (uint4*)(smemf + 8704);        // [1024]     16384 B

    const int tid = threadIdx.x;
    const int warp = tid >> 5, lane = tid & 31;
    const int g = lane >> 2, q = lane & 3;
    const int blockRow = blockIdx.x * 128;

    const uint32_t xs_a = smem_u32(xs);
    const uint32_t wf_a = smem_u32(wf);

    float d[8][4];
#pragma unroll
    for (int j = 0; j < 8; j++)
#pragma unroll
        for (int i = 0; i < 4; i++) d[j][i] = 0.0f;

    const int r0 = warp * 16 + g;
    const int r1 = r0 + 8;

    for (int ch = 0; ch < 8; ch++) {
        __syncthreads();
        const float* xsrc = x + (size_t)blockRow * 512 + ch * 64;
#pragma unroll
        for (int it = 0; it < 8; it++) {
            int fidx = it * 256 + tid;
            int rr = fidx >> 4, c4 = (fidx & 15) * 4;
            cpa16(xs_a + (rr * 68 + c4) * 4, xsrc + (size_t)rr * 512 + c4);
        }
        const uint4* sp = g_w1h + ch * 1024;
#pragma unroll
        for (int i = 0; i < 4; i++)
            cpa16(wf_a + (i * 256 + tid) * 16, sp + i * 256 + tid);
        CPA_COMMIT();
        CPA_WAIT0();
        __syncthreads();

#pragma unroll
        for (int ks = 0; ks < 4; ks++) {
            const int lc = ks * 16 + 2 * q;
            float2 f00 = *(const float2*)&xs[r0 * 68 + lc];
            float2 f10 = *(const float2*)&xs[r1 * 68 + lc];
            float2 f08 = *(const float2*)&xs[r0 * 68 + lc + 8];
            float2 f18 = *(const float2*)&xs[r1 * 68 + lc + 8];
            unsigned ahi[4], alo[4];
            ahi[0] = split_hl(f00, alo[0]);
            ahi[1] = split_hl(f10, alo[1]);
            ahi[2] = split_hl(f08, alo[2]);
            ahi[3] = split_hl(f18, alo[3]);

            const int base = ks * 256 + lane;
#pragma unroll
            for (int j = 0; j < 8; j++) {
                uint4 w = wf[base + j * 32];
                mma16816h(d[j], ahi, w.x, w.y);   // hi * hi
                mma16816h(d[j], ahi, w.z, w.w);   // hi * lo
                mma16816h(d[j], alo, w.x, w.y);   // lo * hi
            }
        }
    }

    float* o0 = &g_hin[(size_t)(blockRow + r0) * 64];
    float* o1 = &g_hin[(size_t)(blockRow + r1) * 64];
#pragma unroll
    for (int j = 0; j < 8; j++) {
        const float2 bb = *(const float2*)&b1[8 * j + 2 * q];
        float2 v0 = make_float2(d[j][0] + bb.x, d[j][1] + bb.y);
        float2 v1 = make_float2(d[j][2] + bb.x, d[j][3] + bb.y);
        *(float2*)&o0[8 * j + 2 * q] = v0;
        *(float2*)&o1[8 * j + 2 * q] = v1;
    }
}

// ---------------------------------------------------------------------------
// Kernel 2: LIF recurrence with nibble LUTs; warp handles 8 rows. (unchanged)
// ---------------------------------------------------------------------------
__global__ void __launch_bounds__(256) k2_recur(const float* __restrict__ W2,
                                                const float* __restrict__ b2,
                                                const float* __restrict__ W3,
                                                const float* __restrict__ b3) {
    __shared__ float  LUT2[16 * 16 * 16];
    __shared__ float2 LUT3p[4 * 16 * 32];

    const int tid = threadIdx.x;
    for (int e = tid; e < 4096; e += 256) {
        int np = e >> 8, nv = (e >> 4) & 15, i = e & 15;
        float s = 0.0f;
#pragma unroll
        for (int j = 0; j < 4; j++)
            if (nv & (1 << j)) s += W2[i * 64 + np * 4 + j];
        LUT2[e] = s;
    }
    for (int e = tid; e < 2048; e += 256) {
        int np = e >> 9, nv = (e >> 5) & 15, j = e & 31;
        float sx = 0.0f, sy = 0.0f;
#pragma unroll
        for (int jj = 0; jj < 4; jj++)
            if (nv & (1 << jj)) {
                sx += W3[j * 16 + np * 4 + jj];
                sy += W3[(j + 32) * 16 + np * 4 + jj];
            }
        LUT3p[e] = make_float2(sx, sy);
    }
    __syncthreads();

    const int warp = tid >> 5, lane = tid & 31;
    const int row0 = blockIdx.x * 64 + warp * 8;
    const int iL = lane & 15;
    const int half = lane >> 4;
    const float b2v = b2[iL];
    const float b3a = b3[lane];
    const float b3b = b3[lane + 32];

    float h0[8], h1[8], v1a[8], v1b[8], v2[8], v3a[8], v3b[8];
#pragma unroll
    for (int r = 0; r < 8; r++) {
        h0[r] = g_hin[(size_t)(row0 + r) * 64 + lane];
        h1[r] = g_hin[(size_t)(row0 + r) * 64 + 32 + lane];
        v1a[r] = v1b[r] = v2[r] = v3a[r] = v3b[r] = 0.0f;
    }

    for (int t = 0; t < 8; t++) {
        unsigned mlo[8], mhi[8];
#pragma unroll
        for (int r = 0; r < 8; r++) {
            v1a[r] += (h0[r] - v1a[r]) * 0.5f;
            bool s1a = v1a[r] >= 1.0f;
            if (s1a) v1a[r] = 0.0f;
            v1b[r] += (h1[r] - v1b[r]) * 0.5f;
            bool s1b = v1b[r] >= 1.0f;
            if (s1b) v1b[r] = 0.0f;
            mlo[r] = __ballot_sync(0xffffffffu, s1a);
            mhi[r] = __ballot_sync(0xffffffffu, s1b);
        }

#pragma unroll
        for (int r = 0; r < 8; r++) {
            unsigned w = half ? mhi[r] : mlo[r];
            float p2 = 0.0f;
#pragma unroll
            for (int p = 0; p < 8; p++) {
                unsigned nv = (w >> (4 * p)) & 15u;
                p2 += LUT2[(half * 8 + p) * 256 + nv * 16 + iL];
            }
            p2 += __shfl_xor_sync(0xffffffffu, p2, 16);
            float a2 = b2v + p2;
            v2[r] += (a2 - v2[r]) * 0.5f;
            bool s2 = v2[r] >= 1.0f;
            if (s2) v2[r] = 0.0f;
            unsigned m2 = __ballot_sync(0xffffffffu, s2) & 0xFFFFu;

            float i3a = b3a, i3b = b3b;
#pragma unroll
            for (int p = 0; p < 4; p++) {
                unsigned nv = (m2 >> (4 * p)) & 15u;
                float2 L = LUT3p[(p * 16 + nv) * 32 + lane];
                i3a += L.x;
                i3b += L.y;
            }
            v3a[r] += (i3a - v3a[r]) * 0.5f;
            bool s3a = v3a[r] >= 1.0f;
            if (s3a) v3a[r] = 0.0f;
            v3b[r] += (i3b - v3b[r]) * 0.5f;
            bool s3b = v3b[r] >= 1.0f;
            if (s3b) v3b[r] = 0.0f;

            unsigned olo = __ballot_sync(0xffffffffu, s3a);
            unsigned ohi = __ballot_sync(0xffffffffu, s3b);
            unsigned long long mo = ((unsigned long long)ohi << 32) | (unsigned long long)olo;
            if (lane == r) g_masks[(size_t)(row0 + r) * 8 + t] = mo;
        }
    }
}

// ---------------------------------------------------------------------------
// Kernel 3: fp16 HMMA with f16 accumulators; tanh sums kept in half2;
// direct STG epilogue (R8 layout). N = 8 batches, t in registers.
// ---------------------------------------------------------------------------
__global__ void __launch_bounds__(256) k3_mma(const float* __restrict__ b4,
                                              float* __restrict__ out) {
    __shared__ uint4 sf0[8][4][32];   // [t][cc][lane] frag ks0/ks1, 16 KB
    __shared__ uint4 sf1[8][4][32];   // [t][cc][lane] frag ks2/ks3, 16 KB

    const int tid = threadIdx.x;
    const int warp = tid >> 5, lane = tid & 31;
    const int g = lane >> 2;
    const int q = lane & 3;
    const int colbase = blockIdx.y * 128 + warp * 16;
    const int c0 = colbase + g;
    const int c1 = colbase + g + 8;

    // A fragments (0.5*W4 fp16), register-resident
    unsigned af[4][4];
#pragma unroll
    for (int ks = 0; ks < 4; ks++) {
        af[ks][0] = g_w4f[c0 * 32 + ks * 8 + q];
        af[ks][1] = g_w4f[c1 * 32 + ks * 8 + q];
        af[ks][2] = g_w4f[c0 * 32 + ks * 8 + 4 + q];
        af[ks][3] = g_w4f[c1 * 32 + ks * 8 + 4 + q];
    }
    // bias as half2 C-operand init (0.5*b4 folded for tanh identity)
    __half2 ce0 = __float2half2_rn(0.5f * b4[c0]);
    __half2 ce1 = __float2half2_rn(0.5f * b4[c1]);
    const unsigned ce0u = *(unsigned*)&ce0;
    const unsigned ce1u = *(unsigned*)&ce1;

    for (int it = 0; it < 4; it++) {
        const int bbase = blockIdx.x * 128 + it * 32;

        // Producer: warp w builds frags for t = w.
#pragma unroll
        for (int cc = 0; cc < 4; cc++) {
            const unsigned long long m = g_masks[(size_t)(bbase + cc * 8 + g) * 8 + warp];
            unsigned wv[4][2];
#pragma unroll
            for (int ks = 0; ks < 4; ks++) {
                unsigned xx = (unsigned)(m >> (ks * 16 + 2 * q));
                unsigned s0 = (unsigned)((int)(xx << 31) >> 31) & 0x00003C00u;
                unsigned s1 = (unsigned)((int)(xx << 30) >> 31) & 0x3C000000u;
                wv[ks][0] = s0 | s1;
                unsigned yy = (unsigned)(m >> (ks * 16 + 8 + 2 * q));
                unsigned s2 = (unsigned)((int)(yy << 31) >> 31) & 0x00003C00u;
                unsigned s3 = (unsigned)((int)(yy << 30) >> 31) & 0x3C000000u;
                wv[ks][1] = s2 | s3;
            }
            sf0[warp][cc][lane] = make_uint4(wv[0][0], wv[0][1], wv[1][0], wv[1][1]);
            sf1[warp][cc][lane] = make_uint4(wv[2][0], wv[2][1], wv[3][0], wv[3][1]);
        }
        __syncthreads();

        // Consumer: f16-accum MMAs; tanh sums stay in half2.
#pragma unroll
        for (int cc = 0; cc < 4; cc++) {
            __half2 sumA = __float2half2_rn(0.0f);
            __half2 sumB = __float2half2_rn(0.0f);
#pragma unroll
            for (int t = 0; t < 8; t++) {
                uint4 fa = sf0[t][cc][lane];
                uint4 fb = sf1[t][cc][lane];

                unsigned dd[2] = {ce0u, ce1u};   // bias via C
                mma16816hh(dd, af[0], fa.x, fa.y);
                mma16816hh(dd, af[1], fa.z, fa.w);
                mma16816hh(dd, af[2], fb.x, fb.y);
                mma16816hh(dd, af[3], fb.z, fb.w);

                unsigned tA = tanh2(dd[0]);
                unsigned tB = tanh2(dd[1]);
                sumA = __hadd2(sumA, *(__half2*)&tA);
                sumB = __hadd2(sumB, *(__half2*)&tB);
            }
            float2 fA = __half22float2(sumA);
            float2 fB = __half22float2(sumB);
            const int b0 = bbase + cc * 8 + 2 * q;
            out[(size_t)b0 * 512 + c0]       = fmaf(fA.x, 0.0625f, 0.5f);
            out[(size_t)(b0 + 1) * 512 + c0] = fmaf(fA.y, 0.0625f, 0.5f);
            out[(size_t)b0 * 512 + c1]       = fmaf(fB.x, 0.0625f, 0.5f);
            out[(size_t)(b0 + 1) * 512 + c1] = fmaf(fB.y, 0.0625f, 0.5f);
        }
        __syncthreads();
    }
}

// ---------------------------------------------------------------------------
extern "C" void kernel_launch(void* const* d_in, const int* in_sizes, int n_in,
                              void* d_out, int out_size) {
    const float* x  = (const float*)d_in[0];
    const float* W1 = (const float*)d_in[1];
    const float* b1 = (const float*)d_in[2];
    const float* W2 = (const float*)d_in[3];
    const float* b2 = (const float*)d_in[4];
    const float* W3 = (const float*)d_in[5];
    const float* b3 = (const float*)d_in[6];
    const float* W4 = (const float*)d_in[7];
    const float* b4 = (const float*)d_in[8];
    float* out = (float*)d_out;

    static bool attr_set = false;
    if (!attr_set) {
        cudaFuncSetAttribute(k1_hin, cudaFuncAttributeMaxDynamicSharedMemorySize, 51200);
        attr_set = true;
    }

    k0_pack<<<96, 256>>>(W4, W1);
    k1_hin<<<B_TOTAL / 128, 256, 51200>>>(x, b1);
    k2_recur<<<B_TOTAL / 64, 256>>>(W2, b2, W3, b3);
    k3_mma<<<dim3(B_TOTAL / 128, 4), 256>>>(b4, out);
}

// round 11
// speedup vs baseline: 1.4867x; 1.0602x over previous
#include <cuda_runtime.h>
#include <cuda_fp16.h>
#include <cstdint>

// SNNAutoencoder: B=65536, D=512, H=64, L=16, T=8
// Inputs: x[65536,512], W1[64,512], b1[64], W2[16,64], b2[16],
//         W3[64,16], b3[64], W4[512,64], b4[512]    Output: float32 [65536,512]

#define B_TOTAL 65536

// Scratch (static device arrays)
__device__ float              g_hin[(size_t)B_TOTAL * 64];      // 16 MB
__device__ unsigned long long g_masks[(size_t)B_TOTAL * 8];     //  4 MB packed s3
__device__ unsigned           g_w4f[512 * 32];                  // fp16x2 (0.5*W4) [c][kpair]
__device__ uint4              g_w1h[32 * 8 * 32];               // fp16 hi/lo B-frags [ks][j][lane]

// ---------------------------------------------------------------------------
// helpers
// ---------------------------------------------------------------------------
__device__ __forceinline__ unsigned tanh2(unsigned h) {
    unsigned r;
    asm("tanh.approx.f16x2 %0, %1;" : "=r"(r) : "r"(h));
    return r;
}
__device__ __forceinline__ uint32_t smem_u32(const void* p) {
    uint32_t a;
    asm("{ .reg .u64 t; cvta.to.shared.u64 t, %1; cvt.u32.u64 %0, t; }" : "=r"(a) : "l"(p));
    return a;
}
__device__ __forceinline__ void cpa16(uint32_t dst, const void* src) {
    asm volatile("cp.async.ca.shared.global [%0], [%1], 16;" :: "r"(dst), "l"(src));
}
#define CPA_COMMIT() asm volatile("cp.async.commit_group;" ::: "memory")
#define CPA_WAIT0()  asm volatile("cp.async.wait_group 0;" ::: "memory")

// fp16 mma, f32 accum (k1)
__device__ __forceinline__ void mma16816h(float* d, const unsigned* a,
                                          unsigned b0, unsigned b1) {
    asm volatile(
        "mma.sync.aligned.m16n8k16.row.col.f32.f16.f16.f32 "
        "{%0,%1,%2,%3}, {%4,%5,%6,%7}, {%8,%9}, {%0,%1,%2,%3};"
        : "+f"(d[0]), "+f"(d[1]), "+f"(d[2]), "+f"(d[3])
        : "r"(a[0]), "r"(a[1]), "r"(a[2]), "r"(a[3]), "r"(b0), "r"(b1));
}
// fp16 mma, f16 accum (k3): D,C = 2 regs (half2 each)
__device__ __forceinline__ void mma16816hh(unsigned* d, const unsigned* a,
                                           unsigned b0, unsigned b1) {
    asm volatile(
        "mma.sync.aligned.m16n8k16.row.col.f16.f16.f16.f16 "
        "{%0,%1}, {%2,%3,%4,%5}, {%6,%7}, {%0,%1};"
        : "+r"(d[0]), "+r"(d[1])
        : "r"(a[0]), "r"(a[1]), "r"(a[2]), "r"(a[3]), "r"(b0), "r"(b1));
}

// split float2 -> fp16x2 hi + lo (exact residual)
__device__ __forceinline__ unsigned split_hl(float2 f, unsigned& lo) {
    __half2 h = __floats2half2_rn(f.x, f.y);
    float2 hf = __half22float2(h);
    __half2 l = __floats2half2_rn(f.x - hf.x, f.y - hf.y);
    lo = *(unsigned*)&l;
    return *(unsigned*)&h;
}

// ---------------------------------------------------------------------------
// Kernel 0: pack 0.5*W4 (fp16x2) and W1 (fp16 hi/lo B-fragments)
// ---------------------------------------------------------------------------
__global__ void k0_pack(const float* __restrict__ W4,
                        const float* __restrict__ W1) {
    const int bid = blockIdx.x;
    if (bid < 64) {
        const int idx = bid * 256 + threadIdx.x;   // 0..16383
        float w0 = 0.5f * W4[2 * idx], w1 = 0.5f * W4[2 * idx + 1];
        __half h0 = __float2half_rn(w0);
        __half h1 = __float2half_rn(w1);
        g_w4f[idx] = (unsigned)__half_as_ushort(h0) |
                     ((unsigned)__half_as_ushort(h1) << 16);
    } else {
        const int idx = (bid - 64) * 256 + threadIdx.x;   // 0..8191
        int ks = idx >> 8, j = (idx >> 5) & 7, lane = idx & 31;
        int g = lane >> 2, q = lane & 3;
        int n = 8 * j + g;
        const float* src = W1 + n * 512 + ks * 16;
        float2 f0 = make_float2(src[2 * q], src[2 * q + 1]);
        float2 f1 = make_float2(src[8 + 2 * q], src[8 + 2 * q + 1]);
        unsigned lo0, lo1;
        unsigned hi0 = split_hl(f0, lo0);
        unsigned hi1 = split_hl(f1, lo1);
        g_w1h[idx] = make_uint4(hi0, hi1, lo0, lo1);
    }
}

// ---------------------------------------------------------------------------
// Kernel 1: h_in = x @ W1^T + b1 via 3x fp16 mma.sync (hi/lo split).
// ---------------------------------------------------------------------------
__global__ void __launch_bounds__(256) k1_hin(const float* __restrict__ x,
                                              const float* __restrict__ b1) {
    extern __shared__ float smemf[];
    float* xs = smemf;                         // [128][68]  34816 B
    uint4* wf = (uint4*)(smemf + 8704);        // [1024]     16384 B

    const int tid = threadIdx.x;
    const int warp = tid >> 5, lane = tid & 31;
    const int g = lane >> 2, q = lane & 3;
    const int blockRow = blockIdx.x * 128;

    const uint32_t xs_a = smem_u32(xs);
    const uint32_t wf_a = smem_u32(wf);

    float d[8][4];
#pragma unroll
    for (int j = 0; j < 8; j++)
#pragma unroll
        for (int i = 0; i < 4; i++) d[j][i] = 0.0f;

    const int r0 = warp * 16 + g;
    const int r1 = r0 + 8;

    for (int ch = 0; ch < 8; ch++) {
        __syncthreads();
        const float* xsrc = x + (size_t)blockRow * 512 + ch * 64;
#pragma unroll
        for (int it = 0; it < 8; it++) {
            int fidx = it * 256 + tid;
            int rr = fidx >> 4, c4 = (fidx & 15) * 4;
            cpa16(xs_a + (rr * 68 + c4) * 4, xsrc + (size_t)rr * 512 + c4);
        }
        const uint4* sp = g_w1h + ch * 1024;
#pragma unroll
        for (int i = 0; i < 4; i++)
            cpa16(wf_a + (i * 256 + tid) * 16, sp + i * 256 + tid);
        CPA_COMMIT();
        CPA_WAIT0();
        __syncthreads();

#pragma unroll
        for (int ks = 0; ks < 4; ks++) {
            const int lc = ks * 16 + 2 * q;
            float2 f00 = *(const float2*)&xs[r0 * 68 + lc];
            float2 f10 = *(const float2*)&xs[r1 * 68 + lc];
            float2 f08 = *(const float2*)&xs[r0 * 68 + lc + 8];
            float2 f18 = *(const float2*)&xs[r1 * 68 + lc + 8];
            unsigned ahi[4], alo[4];
            ahi[0] = split_hl(f00, alo[0]);
            ahi[1] = split_hl(f10, alo[1]);
            ahi[2] = split_hl(f08, alo[2]);
            ahi[3] = split_hl(f18, alo[3]);

            const int base = ks * 256 + lane;
#pragma unroll
            for (int j = 0; j < 8; j++) {
                uint4 w = wf[base + j * 32];
                mma16816h(d[j], ahi, w.x, w.y);   // hi * hi
                mma16816h(d[j], ahi, w.z, w.w);   // hi * lo
                mma16816h(d[j], alo, w.x, w.y);   // lo * hi
            }
        }
    }

    float* o0 = &g_hin[(size_t)(blockRow + r0) * 64];
    float* o1 = &g_hin[(size_t)(blockRow + r1) * 64];
#pragma unroll
    for (int j = 0; j < 8; j++) {
        const float2 bb = *(const float2*)&b1[8 * j + 2 * q];
        float2 v0 = make_float2(d[j][0] + bb.x, d[j][1] + bb.y);
        float2 v1 = make_float2(d[j][2] + bb.x, d[j][3] + bb.y);
        *(float2*)&o0[8 * j + 2 * q] = v0;
        *(float2*)&o1[8 * j + 2 * q] = v1;
    }
}

// ---------------------------------------------------------------------------
// Kernel 2: LIF recurrence with nibble LUTs; warp handles 8 rows. (unchanged)
// ---------------------------------------------------------------------------
__global__ void __launch_bounds__(256) k2_recur(const float* __restrict__ W2,
                                                const float* __restrict__ b2,
                                                const float* __restrict__ W3,
                                                const float* __restrict__ b3) {
    __shared__ float  LUT2[16 * 16 * 16];
    __shared__ float2 LUT3p[4 * 16 * 32];

    const int tid = threadIdx.x;
    for (int e = tid; e < 4096; e += 256) {
        int np = e >> 8, nv = (e >> 4) & 15, i = e & 15;
        float s = 0.0f;
#pragma unroll
        for (int j = 0; j < 4; j++)
            if (nv & (1 << j)) s += W2[i * 64 + np * 4 + j];
        LUT2[e] = s;
    }
    for (int e = tid; e < 2048; e += 256) {
        int np = e >> 9, nv = (e >> 5) & 15, j = e & 31;
        float sx = 0.0f, sy = 0.0f;
#pragma unroll
        for (int jj = 0; jj < 4; jj++)
            if (nv & (1 << jj)) {
                sx += W3[j * 16 + np * 4 + jj];
                sy += W3[(j + 32) * 16 + np * 4 + jj];
            }
        LUT3p[e] = make_float2(sx, sy);
    }
    __syncthreads();

    const int warp = tid >> 5, lane = tid & 31;
    const int row0 = blockIdx.x * 64 + warp * 8;
    const int iL = lane & 15;
    const int half = lane >> 4;
    const float b2v = b2[iL];
    const float b3a = b3[lane];
    const float b3b = b3[lane + 32];

    float h0[8], h1[8], v1a[8], v1b[8], v2[8], v3a[8], v3b[8];
#pragma unroll
    for (int r = 0; r < 8; r++) {
        h0[r] = g_hin[(size_t)(row0 + r) * 64 + lane];
        h1[r] = g_hin[(size_t)(row0 + r) * 64 + 32 + lane];
        v1a[r] = v1b[r] = v2[r] = v3a[r] = v3b[r] = 0.0f;
    }

    for (int t = 0; t < 8; t++) {
        unsigned mlo[8], mhi[8];
#pragma unroll
        for (int r = 0; r < 8; r++) {
            v1a[r] += (h0[r] - v1a[r]) * 0.5f;
            bool s1a = v1a[r] >= 1.0f;
            if (s1a) v1a[r] = 0.0f;
            v1b[r] += (h1[r] - v1b[r]) * 0.5f;
            bool s1b = v1b[r] >= 1.0f;
            if (s1b) v1b[r] = 0.0f;
            mlo[r] = __ballot_sync(0xffffffffu, s1a);
            mhi[r] = __ballot_sync(0xffffffffu, s1b);
        }

#pragma unroll
        for (int r = 0; r < 8; r++) {
            unsigned w = half ? mhi[r] : mlo[r];
            float p2 = 0.0f;
#pragma unroll
            for (int p = 0; p < 8; p++) {
                unsigned nv = (w >> (4 * p)) & 15u;
                p2 += LUT2[(half * 8 + p) * 256 + nv * 16 + iL];
            }
            p2 += __shfl_xor_sync(0xffffffffu, p2, 16);
            float a2 = b2v + p2;
            v2[r] += (a2 - v2[r]) * 0.5f;
            bool s2 = v2[r] >= 1.0f;
            if (s2) v2[r] = 0.0f;
            unsigned m2 = __ballot_sync(0xffffffffu, s2) & 0xFFFFu;

            float i3a = b3a, i3b = b3b;
#pragma unroll
            for (int p = 0; p < 4; p++) {
                unsigned nv = (m2 >> (4 * p)) & 15u;
                float2 L = LUT3p[(p * 16 + nv) * 32 + lane];
                i3a += L.x;
                i3b += L.y;
            }
            v3a[r] += (i3a - v3a[r]) * 0.5f;
            bool s3a = v3a[r] >= 1.0f;
            if (s3a) v3a[r] = 0.0f;
            v3b[r] += (i3b - v3b[r]) * 0.5f;
            bool s3b = v3b[r] >= 1.0f;
            if (s3b) v3b[r] = 0.0f;

            unsigned olo = __ballot_sync(0xffffffffu, s3a);
            unsigned ohi = __ballot_sync(0xffffffffu, s3b);
            unsigned long long mo = ((unsigned long long)ohi << 32) | (unsigned long long)olo;
            if (lane == r) g_masks[(size_t)(row0 + r) * 8 + t] = mo;
        }
    }
}

// ---------------------------------------------------------------------------
// Kernel 3: fp16 HMMA (f16 accum), warp covers 32 columns -> 8 MMAs per
// 2 LDS.128 (frag reuse doubled, grid.y halved). t accumulated in registers.
// ---------------------------------------------------------------------------
__global__ void __launch_bounds__(256) k3_mma(const float* __restrict__ b4,
                                              float* __restrict__ out) {
    __shared__ uint4 sf0[8][4][32];   // [t][cc][lane] frag ks0/ks1, 16 KB
    __shared__ uint4 sf1[8][4][32];   // [t][cc][lane] frag ks2/ks3, 16 KB

    const int tid = threadIdx.x;
    const int warp = tid >> 5, lane = tid & 31;
    const int g = lane >> 2;
    const int q = lane & 3;
    const int colbase = blockIdx.y * 256 + warp * 32;
    const int c0 = colbase + g;          // tile0: rows c0, c0+8
    const int c2 = colbase + 16 + g;     // tile1: rows c2, c2+8

    // A fragments (0.5*W4 fp16) for both 16-row tiles, register-resident
    unsigned af0[4][4], af1[4][4];
#pragma unroll
    for (int ks = 0; ks < 4; ks++) {
        af0[ks][0] = g_w4f[c0 * 32 + ks * 8 + q];
        af0[ks][1] = g_w4f[(c0 + 8) * 32 + ks * 8 + q];
        af0[ks][2] = g_w4f[c0 * 32 + ks * 8 + 4 + q];
        af0[ks][3] = g_w4f[(c0 + 8) * 32 + ks * 8 + 4 + q];
        af1[ks][0] = g_w4f[c2 * 32 + ks * 8 + q];
        af1[ks][1] = g_w4f[(c2 + 8) * 32 + ks * 8 + q];
        af1[ks][2] = g_w4f[c2 * 32 + ks * 8 + 4 + q];
        af1[ks][3] = g_w4f[(c2 + 8) * 32 + ks * 8 + 4 + q];
    }
    // biases as half2 C-operand init (0.5*b4 folded for tanh identity)
    __half2 h0 = __float2half2_rn(0.5f * b4[c0]);
    __half2 h1 = __float2half2_rn(0.5f * b4[c0 + 8]);
    __half2 h2 = __float2half2_rn(0.5f * b4[c2]);
    __half2 h3 = __float2half2_rn(0.5f * b4[c2 + 8]);
    const unsigned ce0 = *(unsigned*)&h0, ce1 = *(unsigned*)&h1;
    const unsigned ce2 = *(unsigned*)&h2, ce3 = *(unsigned*)&h3;

    for (int it = 0; it < 4; it++) {
        const int bbase = blockIdx.x * 128 + it * 32;

        // Producer: warp w builds frags for t = w.
#pragma unroll
        for (int cc = 0; cc < 4; cc++) {
            const unsigned long long m = g_masks[(size_t)(bbase + cc * 8 + g) * 8 + warp];
            unsigned wv[4][2];
#pragma unroll
            for (int ks = 0; ks < 4; ks++) {
                unsigned xx = (unsigned)(m >> (ks * 16 + 2 * q));
                unsigned s0 = (unsigned)((int)(xx << 31) >> 31) & 0x00003C00u;
                unsigned s1 = (unsigned)((int)(xx << 30) >> 31) & 0x3C000000u;
                wv[ks][0] = s0 | s1;
                unsigned yy = (unsigned)(m >> (ks * 16 + 8 + 2 * q));
                unsigned s2 = (unsigned)((int)(yy << 31) >> 31) & 0x00003C00u;
                unsigned s3 = (unsigned)((int)(yy << 30) >> 31) & 0x3C000000u;
                wv[ks][1] = s2 | s3;
            }
            sf0[warp][cc][lane] = make_uint4(wv[0][0], wv[0][1], wv[1][0], wv[1][1]);
            sf1[warp][cc][lane] = make_uint4(wv[2][0], wv[2][1], wv[3][0], wv[3][1]);
        }
        __syncthreads();

        // Consumer: 8 MMAs per (t,cc) off 2 LDS.128; tanh sums in half2.
#pragma unroll
        for (int cc = 0; cc < 4; cc++) {
            __half2 s00 = __float2half2_rn(0.0f);
            __half2 s01 = __float2half2_rn(0.0f);
            __half2 s10 = __float2half2_rn(0.0f);
            __half2 s11 = __float2half2_rn(0.0f);
#pragma unroll
            for (int t = 0; t < 8; t++) {
                uint4 fa = sf0[t][cc][lane];
                uint4 fb = sf1[t][cc][lane];

                unsigned d0[2] = {ce0, ce1};
                unsigned d1[2] = {ce2, ce3};
                mma16816hh(d0, af0[0], fa.x, fa.y);
                mma16816hh(d1, af1[0], fa.x, fa.y);
                mma16816hh(d0, af0[1], fa.z, fa.w);
                mma16816hh(d1, af1[1], fa.z, fa.w);
                mma16816hh(d0, af0[2], fb.x, fb.y);
                mma16816hh(d1, af1[2], fb.x, fb.y);
                mma16816hh(d0, af0[3], fb.z, fb.w);
                mma16816hh(d1, af1[3], fb.z, fb.w);

                unsigned t00 = tanh2(d0[0]);
                unsigned t01 = tanh2(d0[1]);
                unsigned t10 = tanh2(d1[0]);
                unsigned t11 = tanh2(d1[1]);
                s00 = __hadd2(s00, *(__half2*)&t00);
                s01 = __hadd2(s01, *(__half2*)&t01);
                s10 = __hadd2(s10, *(__half2*)&t10);
                s11 = __hadd2(s11, *(__half2*)&t11);
            }
            float2 f00 = __half22float2(s00);
            float2 f01 = __half22float2(s01);
            float2 f10 = __half22float2(s10);
            float2 f11 = __half22float2(s11);
            const int b0 = bbase + cc * 8 + 2 * q;
            float* ob0 = out + (size_t)b0 * 512;
            float* ob1 = out + (size_t)(b0 + 1) * 512;
            ob0[c0]      = fmaf(f00.x, 0.0625f, 0.5f);
            ob1[c0]      = fmaf(f00.y, 0.0625f, 0.5f);
            ob0[c0 + 8]  = fmaf(f01.x, 0.0625f, 0.5f);
            ob1[c0 + 8]  = fmaf(f01.y, 0.0625f, 0.5f);
            ob0[c2]      = fmaf(f10.x, 0.0625f, 0.5f);
            ob1[c2]      = fmaf(f10.y, 0.0625f, 0.5f);
            ob0[c2 + 8]  = fmaf(f11.x, 0.0625f, 0.5f);
            ob1[c2 + 8]  = fmaf(f11.y, 0.0625f, 0.5f);
        }
        __syncthreads();
    }
}

// ---------------------------------------------------------------------------
extern "C" void kernel_launch(void* const* d_in, const int* in_sizes, int n_in,
                              void* d_out, int out_size) {
    const float* x  = (const float*)d_in[0];
    const float* W1 = (const float*)d_in[1];
    const float* b1 = (const float*)d_in[2];
    const float* W2 = (const float*)d_in[3];
    const float* b2 = (const float*)d_in[4];
    const float* W3 = (const float*)d_in[5];
    const float* b3 = (const float*)d_in[6];
    const float* W4 = (const float*)d_in[7];
    const float* b4 = (const float*)d_in[8];
    float* out = (float*)d_out;

    static bool attr_set = false;
    if (!attr_set) {
        cudaFuncSetAttribute(k1_hin, cudaFuncAttributeMaxDynamicSharedMemorySize, 51200);
        attr_set = true;
    }

    k0_pack<<<96, 256>>>(W4, W1);
    k1_hin<<<B_TOTAL / 128, 256, 51200>>>(x, b1);
    k2_recur<<<B_TOTAL / 64, 256>>>(W2, b2, W3, b3);
    k3_mma<<<dim3(B_TOTAL / 128, 2), 256>>>(b4, out);
}

// round 12
// speedup vs baseline: 1.9550x; 1.3150x over previous
#include <cuda_runtime.h>
#include <cuda_fp16.h>
#include <cstdint>

// SNNAutoencoder: B=65536, D=512, H=64, L=16, T=8
// Inputs: x[65536,512], W1[64,512], b1[64], W2[16,64], b2[16],
//         W3[64,16], b3[64], W4[512,64], b4[512]    Output: float32 [65536,512]

#define B_TOTAL 65536

// Scratch (static device arrays)
__device__ float              g_hin[(size_t)B_TOTAL * 64];      // 16 MB
__device__ unsigned long long g_masks[(size_t)B_TOTAL * 8];     //  4 MB packed s3
__device__ unsigned           g_w4f[512 * 32];                  // fp16x2 (0.5*W4) [c][kpair]
__device__ uint4              g_w1h[32 * 8 * 32];               // fp16 hi/lo B-frags [ks][j][lane]
__device__ uint4              g_w2f[8 * 32];                    // 0.5*W2 hi/lo B-frags [(nc*4+ks)][lane]
__device__ uint4              g_w3f[8 * 32];                    // 0.5*W3 hi/lo B-frags [nc][lane]

// ---------------------------------------------------------------------------
// helpers
// ---------------------------------------------------------------------------
__device__ __forceinline__ unsigned tanh2(unsigned h) {
    unsigned r;
    asm("tanh.approx.f16x2 %0, %1;" : "=r"(r) : "r"(h));
    return r;
}
__device__ __forceinline__ uint32_t smem_u32(const void* p) {
    uint32_t a;
    asm("{ .reg .u64 t; cvta.to.shared.u64 t, %1; cvt.u32.u64 %0, t; }" : "=r"(a) : "l"(p));
    return a;
}
__device__ __forceinline__ void cpa16(uint32_t dst, const void* src) {
    asm volatile("cp.async.ca.shared.global [%0], [%1], 16;" :: "r"(dst), "l"(src));
}
#define CPA_COMMIT() asm volatile("cp.async.commit_group;" ::: "memory")
#define CPA_WAIT0()  asm volatile("cp.async.wait_group 0;" ::: "memory")

// fp16 mma, f32 accum, accumulate into D
__device__ __forceinline__ void mma16816h(float* d, const unsigned* a,
                                          unsigned b0, unsigned b1) {
    asm volatile(
        "mma.sync.aligned.m16n8k16.row.col.f32.f16.f16.f32 "
        "{%0,%1,%2,%3}, {%4,%5,%6,%7}, {%8,%9}, {%0,%1,%2,%3};"
        : "+f"(d[0]), "+f"(d[1]), "+f"(d[2]), "+f"(d[3])
        : "r"(a[0]), "r"(a[1]), "r"(a[2]), "r"(a[3]), "r"(b0), "r"(b1));
}
// fp16 mma, f32 accum, explicit C (bias init)
__device__ __forceinline__ void mma16816h_c(float* d, const unsigned* a,
                                            unsigned b0, unsigned b1,
                                            float c0, float c1, float c2, float c3) {
    asm volatile(
        "mma.sync.aligned.m16n8k16.row.col.f32.f16.f16.f32 "
        "{%0,%1,%2,%3}, {%4,%5,%6,%7}, {%8,%9}, {%10,%11,%12,%13};"
        : "=f"(d[0]), "=f"(d[1]), "=f"(d[2]), "=f"(d[3])
        : "r"(a[0]), "r"(a[1]), "r"(a[2]), "r"(a[3]), "r"(b0), "r"(b1),
          "f"(c0), "f"(c1), "f"(c2), "f"(c3));
}
// fp16 mma, f16 accum (k3)
__device__ __forceinline__ void mma16816hh(unsigned* d, const unsigned* a,
                                           unsigned b0, unsigned b1) {
    asm volatile(
        "mma.sync.aligned.m16n8k16.row.col.f16.f16.f16.f16 "
        "{%0,%1}, {%2,%3,%4,%5}, {%6,%7}, {%0,%1};"
        : "+r"(d[0]), "+r"(d[1])
        : "r"(a[0]), "r"(a[1]), "r"(a[2]), "r"(a[3]), "r"(b0), "r"(b1));
}

// split float2 -> fp16x2 hi + lo (exact residual)
__device__ __forceinline__ unsigned split_hl(float2 f, unsigned& lo) {
    __half2 h = __floats2half2_rn(f.x, f.y);
    float2 hf = __half22float2(h);
    __half2 l = __floats2half2_rn(f.x - hf.x, f.y - hf.y);
    lo = *(unsigned*)&l;
    return *(unsigned*)&h;
}

// ---------------------------------------------------------------------------
// Kernel 0: pack 0.5*W4 (fp16x2), W1 (fp16 hi/lo B-frags),
//           0.5*W2 and 0.5*W3 (fp16 hi/lo B-frags for k2's MMAs)
// ---------------------------------------------------------------------------
__global__ void k0_pack(const float* __restrict__ W4,
                        const float* __restrict__ W1,
                        const float* __restrict__ W2,
                        const float* __restrict__ W3) {
    const int bid = blockIdx.x;
    const int tid = threadIdx.x;
    if (bid < 64) {
        const int idx = bid * 256 + tid;
        float w0 = 0.5f * W4[2 * idx], w1 = 0.5f * W4[2 * idx + 1];
        __half h0 = __float2half_rn(w0);
        __half h1 = __float2half_rn(w1);
        g_w4f[idx] = (unsigned)__half_as_ushort(h0) |
                     ((unsigned)__half_as_ushort(h1) << 16);
    } else if (bid < 96) {
        const int idx = (bid - 64) * 256 + tid;
        int ks = idx >> 8, j = (idx >> 5) & 7, lane = idx & 31;
        int g = lane >> 2, q = lane & 3;
        int n = 8 * j + g;
        const float* src = W1 + n * 512 + ks * 16;
        float2 f0 = make_float2(src[2 * q], src[2 * q + 1]);
        float2 f1 = make_float2(src[8 + 2 * q], src[8 + 2 * q + 1]);
        unsigned lo0, lo1;
        unsigned hi0 = split_hl(f0, lo0);
        unsigned hi1 = split_hl(f1, lo1);
        g_w1h[idx] = make_uint4(hi0, hi1, lo0, lo1);
    } else if (bid == 96) {
        // W2 frags: set = nc*4+ks; lane (g,q): i = 8nc+g, k = 16ks+2q(+1), +8
        int lane = tid & 31, set = tid >> 5;
        int nc = set >> 2, ks = set & 3;
        int g = lane >> 2, q = lane & 3;
        int i = 8 * nc + g;
        int k = 16 * ks + 2 * q;
        float2 f0 = make_float2(0.5f * W2[i * 64 + k], 0.5f * W2[i * 64 + k + 1]);
        float2 f1 = make_float2(0.5f * W2[i * 64 + k + 8], 0.5f * W2[i * 64 + k + 9]);
        unsigned lo0, lo1;
        unsigned hi0 = split_hl(f0, lo0);
        unsigned hi1 = split_hl(f1, lo1);
        g_w2f[set * 32 + lane] = make_uint4(hi0, hi1, lo0, lo1);
    } else {
        // W3 frags: nc = tid>>5; lane (g,q): j = 8nc+g, k = 2q(+1), +8
        int lane = tid & 31, nc = tid >> 5;
        int g = lane >> 2, q = lane & 3;
        int j = 8 * nc + g;
        float2 f0 = make_float2(0.5f * W3[j * 16 + 2 * q], 0.5f * W3[j * 16 + 2 * q + 1]);
        float2 f1 = make_float2(0.5f * W3[j * 16 + 2 * q + 8], 0.5f * W3[j * 16 + 2 * q + 9]);
        unsigned lo0, lo1;
        unsigned hi0 = split_hl(f0, lo0);
        unsigned hi1 = split_hl(f1, lo1);
        g_w3f[nc * 32 + lane] = make_uint4(hi0, hi1, lo0, lo1);
    }
}

// ---------------------------------------------------------------------------
// Kernel 1: h_in = x @ W1^T + b1 via 3x fp16 mma.sync (hi/lo split). unchanged
// ---------------------------------------------------------------------------
__global__ void __launch_bounds__(256) k1_hin(const float* __restrict__ x,
                                              const float* __restrict__ b1) {
    extern __shared__ float smemf[];
    float* xs = smemf;                         // [128][68]  34816 B
    uint4* wf = (uint4*)(smemf + 8704);        // [1024]     16384 B

    const int tid = threadIdx.x;
    const int warp = tid >> 5, lane = tid & 31;
    const int g = lane >> 2, q = lane & 3;
    const int blockRow = blockIdx.x * 128;

    const uint32_t xs_a = smem_u32(xs);
    const uint32_t wf_a = smem_u32(wf);

    float d[8][4];
#pragma unroll
    for (int j = 0; j < 8; j++)
#pragma unroll
        for (int i = 0; i < 4; i++) d[j][i] = 0.0f;

    const int r0 = warp * 16 + g;
    const int r1 = r0 + 8;

    for (int ch = 0; ch < 8; ch++) {
        __syncthreads();
        const float* xsrc = x + (size_t)blockRow * 512 + ch * 64;
#pragma unroll
        for (int it = 0; it < 8; it++) {
            int fidx = it * 256 + tid;
            int rr = fidx >> 4, c4 = (fidx & 15) * 4;
            cpa16(xs_a + (rr * 68 + c4) * 4, xsrc + (size_t)rr * 512 + c4);
        }
        const uint4* sp = g_w1h + ch * 1024;
#pragma unroll
        for (int i = 0; i < 4; i++)
            cpa16(wf_a + (i * 256 + tid) * 16, sp + i * 256 + tid);
        CPA_COMMIT();
        CPA_WAIT0();
        __syncthreads();

#pragma unroll
        for (int ks = 0; ks < 4; ks++) {
            const int lc = ks * 16 + 2 * q;
            float2 f00 = *(const float2*)&xs[r0 * 68 + lc];
            float2 f10 = *(const float2*)&xs[r1 * 68 + lc];
            float2 f08 = *(const float2*)&xs[r0 * 68 + lc + 8];
            float2 f18 = *(const float2*)&xs[r1 * 68 + lc + 8];
            unsigned ahi[4], alo[4];
            ahi[0] = split_hl(f00, alo[0]);
            ahi[1] = split_hl(f10, alo[1]);
            ahi[2] = split_hl(f08, alo[2]);
            ahi[3] = split_hl(f18, alo[3]);

            const int base = ks * 256 + lane;
#pragma unroll
            for (int j = 0; j < 8; j++) {
                uint4 w = wf[base + j * 32];
                mma16816h(d[j], ahi, w.x, w.y);   // hi * hi
                mma16816h(d[j], ahi, w.z, w.w);   // hi * lo
                mma16816h(d[j], alo, w.x, w.y);   // lo * hi
            }
        }
    }

    float* o0 = &g_hin[(size_t)(blockRow + r0) * 64];
    float* o1 = &g_hin[(size_t)(blockRow + r1) * 64];
#pragma unroll
    for (int j = 0; j < 8; j++) {
        const float2 bb = *(const float2*)&b1[8 * j + 2 * q];
        float2 v0 = make_float2(d[j][0] + bb.x, d[j][1] + bb.y);
        float2 v1 = make_float2(d[j][2] + bb.x, d[j][3] + bb.y);
        *(float2*)&o0[8 * j + 2 * q] = v0;
        *(float2*)&o1[8 * j + 2 * q] = v1;
    }
}

// ---------------------------------------------------------------------------
// Kernel 2: LIF recurrence via tensor-core MMAs. Warp = 16 rows (M=16).
// Layer1 scalar f32 -> spikes packed directly as A-fragments.
// Layer2/3: m16n8k16 f32-accum, hi/lo fp16 weights (exact), 0.5+bias folded.
// Masks: predicated bit-OR + shfl-butterfly over the q-quad. No ballots, no LUTs.
// ---------------------------------------------------------------------------
#define LIF1(VV, HH, BIT, FR) { float nv_ = fmaf(VV, 0.5f, HH); \
    bool s_ = nv_ >= 1.0f; (VV) = s_ ? 0.0f : nv_; if (s_) (FR) |= (BIT); }

__global__ void __launch_bounds__(128) k2_recur(const float* __restrict__ b2,
                                                const float* __restrict__ b3) {
    __shared__ float hs[64][68];       // 0.5*h staged, padded
    __shared__ uint4 w2s[8][32];
    __shared__ uint4 w3s[8][32];

    const int tid = threadIdx.x;
    const int warp = tid >> 5, lane = tid & 31;
    const int g = lane >> 2, q = lane & 3;
    const int row0 = blockIdx.x * 64;

    // stage 0.5*h for 64 rows
    for (int i = tid; i < 1024; i += 128) {
        int r = i >> 4, c4 = (i & 15) * 4;
        float4 v = *(const float4*)&g_hin[(size_t)(row0 + r) * 64 + c4];
        v.x *= 0.5f; v.y *= 0.5f; v.z *= 0.5f; v.w *= 0.5f;
        *(float4*)&hs[r][c4] = v;
    }
    for (int i = tid; i < 256; i += 128) {
        ((uint4*)w2s)[i] = g_w2f[i];
        ((uint4*)w3s)[i] = g_w3f[i];
    }
    __syncthreads();

    const int rA = warp * 16 + g;
    const int rB = rA + 8;

    // biases (0.5-scaled), fed via MMA C operand
    float b2c[2][2], b3c[8][2];
#pragma unroll
    for (int nc = 0; nc < 2; nc++) {
        b2c[nc][0] = 0.5f * b2[8 * nc + 2 * q];
        b2c[nc][1] = 0.5f * b2[8 * nc + 2 * q + 1];
    }
#pragma unroll
    for (int nc = 0; nc < 8; nc++) {
        b3c[nc][0] = 0.5f * b3[8 * nc + 2 * q];
        b3c[nc][1] = 0.5f * b3[8 * nc + 2 * q + 1];
    }
    const unsigned be = 1u << (2 * q);   // even-col mask bit (within byte)
    const unsigned bo = be << 1;         // odd-col

    float v1[4][8];
    float v2[2][4];
    float v3[8][4];
#pragma unroll
    for (int ks = 0; ks < 4; ks++)
#pragma unroll
        for (int i = 0; i < 8; i++) v1[ks][i] = 0.0f;
#pragma unroll
    for (int nc = 0; nc < 2; nc++)
#pragma unroll
        for (int i = 0; i < 4; i++) v2[nc][i] = 0.0f;
#pragma unroll
    for (int nc = 0; nc < 8; nc++)
#pragma unroll
        for (int i = 0; i < 4; i++) v3[nc][i] = 0.0f;

    for (int t = 0; t < 8; t++) {
        // ---- layer 1 + layer 2 MMAs (interleaved per ks) ----
        float d2[2][4];
#pragma unroll
        for (int ks = 0; ks < 4; ks++) {
            const int c0 = 16 * ks + 2 * q;
            float2 hA0 = *(const float2*)&hs[rA][c0];
            float2 hB0 = *(const float2*)&hs[rB][c0];
            float2 hA1 = *(const float2*)&hs[rA][c0 + 8];
            float2 hB1 = *(const float2*)&hs[rB][c0 + 8];

            unsigned aw[4] = {0u, 0u, 0u, 0u};
            LIF1(v1[ks][0], hA0.x, 0x00003C00u, aw[0]);
            LIF1(v1[ks][1], hA0.y, 0x3C000000u, aw[0]);
            LIF1(v1[ks][2], hB0.x, 0x00003C00u, aw[1]);
            LIF1(v1[ks][3], hB0.y, 0x3C000000u, aw[1]);
            LIF1(v1[ks][4], hA1.x, 0x00003C00u, aw[2]);
            LIF1(v1[ks][5], hA1.y, 0x3C000000u, aw[2]);
            LIF1(v1[ks][6], hB1.x, 0x00003C00u, aw[3]);
            LIF1(v1[ks][7], hB1.y, 0x3C000000u, aw[3]);

#pragma unroll
            for (int nc = 0; nc < 2; nc++) {
                uint4 w = w2s[nc * 4 + ks][lane];
                if (ks == 0)
                    mma16816h_c(d2[nc], aw, w.x, w.y,
                                b2c[nc][0], b2c[nc][1], b2c[nc][0], b2c[nc][1]);
                else
                    mma16816h(d2[nc], aw, w.x, w.y);
                mma16816h(d2[nc], aw, w.z, w.w);
            }
        }

        // ---- v2 update + s2 fragments ----
        unsigned s2f[4];
#pragma unroll
        for (int nc = 0; nc < 2; nc++) {
            unsigned frA = 0u, frB = 0u;
            LIF1(v2[nc][0], d2[nc][0], 0x00003C00u, frA);
            LIF1(v2[nc][1], d2[nc][1], 0x3C000000u, frA);
            LIF1(v2[nc][2], d2[nc][2], 0x00003C00u, frB);
            LIF1(v2[nc][3], d2[nc][3], 0x3C000000u, frB);
            s2f[nc * 2]     = frA;   // nc0: a0 (rowA k=2q..), nc1: a2 (rowA k=8+2q..)
            s2f[nc * 2 + 1] = frB;   // a1 / a3 (rowB)
        }

        // ---- layer 3 MMAs + v3 update + mask bits ----
        unsigned mA0 = 0u, mA1 = 0u, mB0 = 0u, mB1 = 0u;
#pragma unroll
        for (int nc = 0; nc < 8; nc++) {
            uint4 w = w3s[nc][lane];
            float d3[4];
            mma16816h_c(d3, s2f, w.x, w.y,
                        b3c[nc][0], b3c[nc][1], b3c[nc][0], b3c[nc][1]);
            mma16816h(d3, s2f, w.z, w.w);

            const unsigned bitE = be << (8 * (nc & 3));
            const unsigned bitO = bo << (8 * (nc & 3));
            {
                float nv = fmaf(v3[nc][0], 0.5f, d3[0]);
                bool s = nv >= 1.0f; v3[nc][0] = s ? 0.0f : nv;
                if (s) { if (nc < 4) mA0 |= bitE; else mA1 |= bitE; }
            }
            {
                float nv = fmaf(v3[nc][1], 0.5f, d3[1]);
                bool s = nv >= 1.0f; v3[nc][1] = s ? 0.0f : nv;
                if (s) { if (nc < 4) mA0 |= bitO; else mA1 |= bitO; }
            }
            {
                float nv = fmaf(v3[nc][2], 0.5f, d3[2]);
                bool s = nv >= 1.0f; v3[nc][2] = s ? 0.0f : nv;
                if (s) { if (nc < 4) mB0 |= bitE; else mB1 |= bitE; }
            }
            {
                float nv = fmaf(v3[nc][3], 0.5f, d3[3]);
                bool s = nv >= 1.0f; v3[nc][3] = s ? 0.0f : nv;
                if (s) { if (nc < 4) mB0 |= bitO; else mB1 |= bitO; }
            }
        }

        // ---- butterfly-OR over the q-quad, then store masks ----
        mA0 |= __shfl_xor_sync(0xffffffffu, mA0, 1);
        mA1 |= __shfl_xor_sync(0xffffffffu, mA1, 1);
        mB0 |= __shfl_xor_sync(0xffffffffu, mB0, 1);
        mB1 |= __shfl_xor_sync(0xffffffffu, mB1, 1);
        mA0 |= __shfl_xor_sync(0xffffffffu, mA0, 2);
        mA1 |= __shfl_xor_sync(0xffffffffu, mA1, 2);
        mB0 |= __shfl_xor_sync(0xffffffffu, mB0, 2);
        mB1 |= __shfl_xor_sync(0xffffffffu, mB1, 2);

        if (q == 0) {
            g_masks[(size_t)(row0 + rA) * 8 + t] =
                (unsigned long long)mA0 | ((unsigned long long)mA1 << 32);
            g_masks[(size_t)(row0 + rB) * 8 + t] =
                (unsigned long long)mB0 | ((unsigned long long)mB1 << 32);
        }
    }
}

// ---------------------------------------------------------------------------
// Kernel 3: fp16 HMMA (f16 accum), warp covers 32 columns. (unchanged)
// ---------------------------------------------------------------------------
__global__ void __launch_bounds__(256) k3_mma(const float* __restrict__ b4,
                                              float* __restrict__ out) {
    __shared__ uint4 sf0[8][4][32];
    __shared__ uint4 sf1[8][4][32];

    const int tid = threadIdx.x;
    const int warp = tid >> 5, lane = tid & 31;
    const int g = lane >> 2;
    const int q = lane & 3;
    const int colbase = blockIdx.y * 256 + warp * 32;
    const int c0 = colbase + g;
    const int c2 = colbase + 16 + g;

    unsigned af0[4][4], af1[4][4];
#pragma unroll
    for (int ks = 0; ks < 4; ks++) {
        af0[ks][0] = g_w4f[c0 * 32 + ks * 8 + q];
        af0[ks][1] = g_w4f[(c0 + 8) * 32 + ks * 8 + q];
        af0[ks][2] = g_w4f[c0 * 32 + ks * 8 + 4 + q];
        af0[ks][3] = g_w4f[(c0 + 8) * 32 + ks * 8 + 4 + q];
        af1[ks][0] = g_w4f[c2 * 32 + ks * 8 + q];
        af1[ks][1] = g_w4f[(c2 + 8) * 32 + ks * 8 + q];
        af1[ks][2] = g_w4f[c2 * 32 + ks * 8 + 4 + q];
        af1[ks][3] = g_w4f[(c2 + 8) * 32 + ks * 8 + 4 + q];
    }
    __half2 h0 = __float2half2_rn(0.5f * b4[c0]);
    __half2 h1 = __float2half2_rn(0.5f * b4[c0 + 8]);
    __half2 h2 = __float2half2_rn(0.5f * b4[c2]);
    __half2 h3 = __float2half2_rn(0.5f * b4[c2 + 8]);
    const unsigned ce0 = *(unsigned*)&h0, ce1 = *(unsigned*)&h1;
    const unsigned ce2 = *(unsigned*)&h2, ce3 = *(unsigned*)&h3;

    for (int it = 0; it < 4; it++) {
        const int bbase = blockIdx.x * 128 + it * 32;

#pragma unroll
        for (int cc = 0; cc < 4; cc++) {
            const unsigned long long m = g_masks[(size_t)(bbase + cc * 8 + g) * 8 + warp];
            unsigned wv[4][2];
#pragma unroll
            for (int ks = 0; ks < 4; ks++) {
                unsigned xx = (unsigned)(m >> (ks * 16 + 2 * q));
                unsigned s0 = (unsigned)((int)(xx << 31) >> 31) & 0x00003C00u;
                unsigned s1 = (unsigned)((int)(xx << 30) >> 31) & 0x3C000000u;
                wv[ks][0] = s0 | s1;
                unsigned yy = (unsigned)(m >> (ks * 16 + 8 + 2 * q));
                unsigned s2 = (unsigned)((int)(yy << 31) >> 31) & 0x00003C00u;
                unsigned s3 = (unsigned)((int)(yy << 30) >> 31) & 0x3C000000u;
                wv[ks][1] = s2 | s3;
            }
            sf0[warp][cc][lane] = make_uint4(wv[0][0], wv[0][1], wv[1][0], wv[1][1]);
            sf1[warp][cc][lane] = make_uint4(wv[2][0], wv[2][1], wv[3][0], wv[3][1]);
        }
        __syncthreads();

#pragma unroll
        for (int cc = 0; cc < 4; cc++) {
            __half2 s00 = __float2half2_rn(0.0f);
            __half2 s01 = __float2half2_rn(0.0f);
            __half2 s10 = __float2half2_rn(0.0f);
            __half2 s11 = __float2half2_rn(0.0f);
#pragma unroll
            for (int t = 0; t < 8; t++) {
                uint4 fa = sf0[t][cc][lane];
                uint4 fb = sf1[t][cc][lane];

                unsigned d0[2] = {ce0, ce1};
                unsigned d1[2] = {ce2, ce3};
                mma16816hh(d0, af0[0], fa.x, fa.y);
                mma16816hh(d1, af1[0], fa.x, fa.y);
                mma16816hh(d0, af0[1], fa.z, fa.w);
                mma16816hh(d1, af1[1], fa.z, fa.w);
                mma16816hh(d0, af0[2], fb.x, fb.y);
                mma16816hh(d1, af1[2], fb.x, fb.y);
                mma16816hh(d0, af0[3], fb.z, fb.w);
                mma16816hh(d1, af1[3], fb.z, fb.w);

                unsigned t00 = tanh2(d0[0]);
                unsigned t01 = tanh2(d0[1]);
                unsigned t10 = tanh2(d1[0]);
                unsigned t11 = tanh2(d1[1]);
                s00 = __hadd2(s00, *(__half2*)&t00);
                s01 = __hadd2(s01, *(__half2*)&t01);
                s10 = __hadd2(s10, *(__half2*)&t10);
                s11 = __hadd2(s11, *(__half2*)&t11);
            }
            float2 f00 = __half22float2(s00);
            float2 f01 = __half22float2(s01);
            float2 f10 = __half22float2(s10);
            float2 f11 = __half22float2(s11);
            const int b0 = bbase + cc * 8 + 2 * q;
            float* ob0 = out + (size_t)b0 * 512;
            float* ob1 = out + (size_t)(b0 + 1) * 512;
            ob0[c0]      = fmaf(f00.x, 0.0625f, 0.5f);
            ob1[c0]      = fmaf(f00.y, 0.0625f, 0.5f);
            ob0[c0 + 8]  = fmaf(f01.x, 0.0625f, 0.5f);
            ob1[c0 + 8]  = fmaf(f01.y, 0.0625f, 0.5f);
            ob0[c2]      = fmaf(f10.x, 0.0625f, 0.5f);
            ob1[c2]      = fmaf(f10.y, 0.0625f, 0.5f);
            ob0[c2 + 8]  = fmaf(f11.x, 0.0625f, 0.5f);
            ob1[c2 + 8]  = fmaf(f11.y, 0.0625f, 0.5f);
        }
        __syncthreads();
    }
}

// ---------------------------------------------------------------------------
extern "C" void kernel_launch(void* const* d_in, const int* in_sizes, int n_in,
                              void* d_out, int out_size) {
    const float* x  = (const float*)d_in[0];
    const float* W1 = (const float*)d_in[1];
    const float* b1 = (const float*)d_in[2];
    const float* W2 = (const float*)d_in[3];
    const float* b2 = (const float*)d_in[4];
    const float* W3 = (const float*)d_in[5];
    const float* b3 = (const float*)d_in[6];
    const float* W4 = (const float*)d_in[7];
    const float* b4 = (const float*)d_in[8];
    float* out = (float*)d_out;

    static bool attr_set = false;
    if (!attr_set) {
        cudaFuncSetAttribute(k1_hin, cudaFuncAttributeMaxDynamicSharedMemorySize, 51200);
        attr_set = true;
    }

    k0_pack<<<98, 256>>>(W4, W1, W2, W3);
    k1_hin<<<B_TOTAL / 128, 256, 51200>>>(x, b1);
    k2_recur<<<B_TOTAL / 64, 128>>>(b2, b3);
    k3_mma<<<dim3(B_TOTAL / 128, 2), 256>>>(b4, out);
}

// round 13
// speedup vs baseline: 1.9557x; 1.0004x over previous
#include <cuda_runtime.h>
#include <cuda_fp16.h>
#include <cstdint>

// SNNAutoencoder: B=65536, D=512, H=64, L=16, T=8
// Inputs: x[65536,512], W1[64,512], b1[64], W2[16,64], b2[16],
//         W3[64,16], b3[64], W4[512,64], b4[512]    Output: float32 [65536,512]

#define B_TOTAL 65536

// Scratch (static device arrays)
__device__ float              g_hin[(size_t)B_TOTAL * 64];      // 16 MB
__device__ unsigned long long g_masks[(size_t)B_TOTAL * 8];     //  4 MB packed s3
__device__ unsigned           g_w4f[512 * 32];                  // fp16x2 (0.5*W4) [c][kpair]
__device__ uint4              g_w1h[32 * 8 * 32];               // fp16 hi/lo B-frags [ks][j][lane]
__device__ uint4              g_w2f[8 * 32];                    // 0.5*W2 hi/lo B-frags [(nc*4+ks)][lane]
__device__ uint4              g_w3f[8 * 32];                    // 0.5*W3 hi/lo B-frags [nc][lane]

// ---------------------------------------------------------------------------
// helpers
// ---------------------------------------------------------------------------
__device__ __forceinline__ unsigned tanh2(unsigned h) {
    unsigned r;
    asm("tanh.approx.f16x2 %0, %1;" : "=r"(r) : "r"(h));
    return r;
}
__device__ __forceinline__ uint32_t smem_u32(const void* p) {
    uint32_t a;
    asm("{ .reg .u64 t; cvta.to.shared.u64 t, %1; cvt.u32.u64 %0, t; }" : "=r"(a) : "l"(p));
    return a;
}
__device__ __forceinline__ void cpa16(uint32_t dst, const void* src) {
    asm volatile("cp.async.ca.shared.global [%0], [%1], 16;" :: "r"(dst), "l"(src));
}
#define CPA_COMMIT() asm volatile("cp.async.commit_group;" ::: "memory")
#define CPA_WAIT0()  asm volatile("cp.async.wait_group 0;" ::: "memory")

// fp16 mma, f32 accum, accumulate into D
__device__ __forceinline__ void mma16816h(float* d, const unsigned* a,
                                          unsigned b0, unsigned b1) {
    asm volatile(
        "mma.sync.aligned.m16n8k16.row.col.f32.f16.f16.f32 "
        "{%0,%1,%2,%3}, {%4,%5,%6,%7}, {%8,%9}, {%0,%1,%2,%3};"
        : "+f"(d[0]), "+f"(d[1]), "+f"(d[2]), "+f"(d[3])
        : "r"(a[0]), "r"(a[1]), "r"(a[2]), "r"(a[3]), "r"(b0), "r"(b1));
}
// fp16 mma, f32 accum, explicit C (bias init)
__device__ __forceinline__ void mma16816h_c(float* d, const unsigned* a,
                                            unsigned b0, unsigned b1,
                                            float c0, float c1, float c2, float c3) {
    asm volatile(
        "mma.sync.aligned.m16n8k16.row.col.f32.f16.f16.f32 "
        "{%0,%1,%2,%3}, {%4,%5,%6,%7}, {%8,%9}, {%10,%11,%12,%13};"
        : "=f"(d[0]), "=f"(d[1]), "=f"(d[2]), "=f"(d[3])
        : "r"(a[0]), "r"(a[1]), "r"(a[2]), "r"(a[3]), "r"(b0), "r"(b1),
          "f"(c0), "f"(c1), "f"(c2), "f"(c3));
}
// fp16 mma, f16 accum (k3)
__device__ __forceinline__ void mma16816hh(unsigned* d, const unsigned* a,
                                           unsigned b0, unsigned b1) {
    asm volatile(
        "mma.sync.aligned.m16n8k16.row.col.f16.f16.f16.f16 "
        "{%0,%1}, {%2,%3,%4,%5}, {%6,%7}, {%0,%1};"
        : "+r"(d[0]), "+r"(d[1])
        : "r"(a[0]), "r"(a[1]), "r"(a[2]), "r"(a[3]), "r"(b0), "r"(b1));
}

// split float2 -> fp16x2 hi + lo (exact residual)
__device__ __forceinline__ unsigned split_hl(float2 f, unsigned& lo) {
    __half2 h = __floats2half2_rn(f.x, f.y);
    float2 hf = __half22float2(h);
    __half2 l = __floats2half2_rn(f.x - hf.x, f.y - hf.y);
    lo = *(unsigned*)&l;
    return *(unsigned*)&h;
}

// ---------------------------------------------------------------------------
// Kernel 0: pack 0.5*W4 (fp16x2), W1 (fp16 hi/lo B-frags),
//           0.5*W2 and 0.5*W3 (fp16 hi/lo B-frags for k2's MMAs)
// ---------------------------------------------------------------------------
__global__ void k0_pack(const float* __restrict__ W4,
                        const float* __restrict__ W1,
                        const float* __restrict__ W2,
                        const float* __restrict__ W3) {
    const int bid = blockIdx.x;
    const int tid = threadIdx.x;
    if (bid < 64) {
        const int idx = bid * 256 + tid;
        float w0 = 0.5f * W4[2 * idx], w1 = 0.5f * W4[2 * idx + 1];
        __half h0 = __float2half_rn(w0);
        __half h1 = __float2half_rn(w1);
        g_w4f[idx] = (unsigned)__half_as_ushort(h0) |
                     ((unsigned)__half_as_ushort(h1) << 16);
    } else if (bid < 96) {
        const int idx = (bid - 64) * 256 + tid;
        int ks = idx >> 8, j = (idx >> 5) & 7, lane = idx & 31;
        int g = lane >> 2, q = lane & 3;
        int n = 8 * j + g;
        const float* src = W1 + n * 512 + ks * 16;
        float2 f0 = make_float2(src[2 * q], src[2 * q + 1]);
        float2 f1 = make_float2(src[8 + 2 * q], src[8 + 2 * q + 1]);
        unsigned lo0, lo1;
        unsigned hi0 = split_hl(f0, lo0);
        unsigned hi1 = split_hl(f1, lo1);
        g_w1h[idx] = make_uint4(hi0, hi1, lo0, lo1);
    } else if (bid == 96) {
        int lane = tid & 31, set = tid >> 5;
        int nc = set >> 2, ks = set & 3;
        int g = lane >> 2, q = lane & 3;
        int i = 8 * nc + g;
        int k = 16 * ks + 2 * q;
        float2 f0 = make_float2(0.5f * W2[i * 64 + k], 0.5f * W2[i * 64 + k + 1]);
        float2 f1 = make_float2(0.5f * W2[i * 64 + k + 8], 0.5f * W2[i * 64 + k + 9]);
        unsigned lo0, lo1;
        unsigned hi0 = split_hl(f0, lo0);
        unsigned hi1 = split_hl(f1, lo1);
        g_w2f[set * 32 + lane] = make_uint4(hi0, hi1, lo0, lo1);
    } else {
        int lane = tid & 31, nc = tid >> 5;
        int g = lane >> 2, q = lane & 3;
        int j = 8 * nc + g;
        float2 f0 = make_float2(0.5f * W3[j * 16 + 2 * q], 0.5f * W3[j * 16 + 2 * q + 1]);
        float2 f1 = make_float2(0.5f * W3[j * 16 + 2 * q + 8], 0.5f * W3[j * 16 + 2 * q + 9]);
        unsigned lo0, lo1;
        unsigned hi0 = split_hl(f0, lo0);
        unsigned hi1 = split_hl(f1, lo1);
        g_w3f[nc * 32 + lane] = make_uint4(hi0, hi1, lo0, lo1);
    }
}

// ---------------------------------------------------------------------------
// Kernel 1: h_in = x @ W1^T + b1 via 3x fp16 mma.sync (hi/lo split). unchanged
// ---------------------------------------------------------------------------
__global__ void __launch_bounds__(256) k1_hin(const float* __restrict__ x,
                                              const float* __restrict__ b1) {
    extern __shared__ float smemf[];
    float* xs = smemf;                         // [128][68]  34816 B
    uint4* wf = (uint4*)(smemf + 8704);        // [1024]     16384 B

    const int tid = threadIdx.x;
    const int warp = tid >> 5, lane = tid & 31;
    const int g = lane >> 2, q = lane & 3;
    const int blockRow = blockIdx.x * 128;

    const uint32_t xs_a = smem_u32(xs);
    const uint32_t wf_a = smem_u32(wf);

    float d[8][4];
#pragma unroll
    for (int j = 0; j < 8; j++)
#pragma unroll
        for (int i = 0; i < 4; i++) d[j][i] = 0.0f;

    const int r0 = warp * 16 + g;
    const int r1 = r0 + 8;

    for (int ch = 0; ch < 8; ch++) {
        __syncthreads();
        const float* xsrc = x + (size_t)blockRow * 512 + ch * 64;
#pragma unroll
        for (int it = 0; it < 8; it++) {
            int fidx = it * 256 + tid;
            int rr = fidx >> 4, c4 = (fidx & 15) * 4;
            cpa16(xs_a + (rr * 68 + c4) * 4, xsrc + (size_t)rr * 512 + c4);
        }
        const uint4* sp = g_w1h + ch * 1024;
#pragma unroll
        for (int i = 0; i < 4; i++)
            cpa16(wf_a + (i * 256 + tid) * 16, sp + i * 256 + tid);
        CPA_COMMIT();
        CPA_WAIT0();
        __syncthreads();

#pragma unroll
        for (int ks = 0; ks < 4; ks++) {
            const int lc = ks * 16 + 2 * q;
            float2 f00 = *(const float2*)&xs[r0 * 68 + lc];
            float2 f10 = *(const float2*)&xs[r1 * 68 + lc];
            float2 f08 = *(const float2*)&xs[r0 * 68 + lc + 8];
            float2 f18 = *(const float2*)&xs[r1 * 68 + lc + 8];
            unsigned ahi[4], alo[4];
            ahi[0] = split_hl(f00, alo[0]);
            ahi[1] = split_hl(f10, alo[1]);
            ahi[2] = split_hl(f08, alo[2]);
            ahi[3] = split_hl(f18, alo[3]);

            const int base = ks * 256 + lane;
#pragma unroll
            for (int j = 0; j < 8; j++) {
                uint4 w = wf[base + j * 32];
                mma16816h(d[j], ahi, w.x, w.y);   // hi * hi
                mma16816h(d[j], ahi, w.z, w.w);   // hi * lo
                mma16816h(d[j], alo, w.x, w.y);   // lo * hi
            }
        }
    }

    float* o0 = &g_hin[(size_t)(blockRow + r0) * 64];
    float* o1 = &g_hin[(size_t)(blockRow + r1) * 64];
#pragma unroll
    for (int j = 0; j < 8; j++) {
        const float2 bb = *(const float2*)&b1[8 * j + 2 * q];
        float2 v0 = make_float2(d[j][0] + bb.x, d[j][1] + bb.y);
        float2 v1 = make_float2(d[j][2] + bb.x, d[j][3] + bb.y);
        *(float2*)&o0[8 * j + 2 * q] = v0;
        *(float2*)&o1[8 * j + 2 * q] = v1;
    }
}

// ---------------------------------------------------------------------------
// Kernel 2: LIF recurrence via tensor-core MMAs. Warp = 16 rows. (unchanged)
// ---------------------------------------------------------------------------
#define LIF1(VV, HH, BIT, FR) { float nv_ = fmaf(VV, 0.5f, HH); \
    bool s_ = nv_ >= 1.0f; (VV) = s_ ? 0.0f : nv_; if (s_) (FR) |= (BIT); }

__global__ void __launch_bounds__(128) k2_recur(const float* __restrict__ b2,
                                                const float* __restrict__ b3) {
    __shared__ float hs[64][68];
    __shared__ uint4 w2s[8][32];
    __shared__ uint4 w3s[8][32];

    const int tid = threadIdx.x;
    const int warp = tid >> 5, lane = tid & 31;
    const int g = lane >> 2, q = lane & 3;
    const int row0 = blockIdx.x * 64;

    for (int i = tid; i < 1024; i += 128) {
        int r = i >> 4, c4 = (i & 15) * 4;
        float4 v = *(const float4*)&g_hin[(size_t)(row0 + r) * 64 + c4];
        v.x *= 0.5f; v.y *= 0.5f; v.z *= 0.5f; v.w *= 0.5f;
        *(float4*)&hs[r][c4] = v;
    }
    for (int i = tid; i < 256; i += 128) {
        ((uint4*)w2s)[i] = g_w2f[i];
        ((uint4*)w3s)[i] = g_w3f[i];
    }
    __syncthreads();

    const int rA = warp * 16 + g;
    const int rB = rA + 8;

    float b2c[2][2], b3c[8][2];
#pragma unroll
    for (int nc = 0; nc < 2; nc++) {
        b2c[nc][0] = 0.5f * b2[8 * nc + 2 * q];
        b2c[nc][1] = 0.5f * b2[8 * nc + 2 * q + 1];
    }
#pragma unroll
    for (int nc = 0; nc < 8; nc++) {
        b3c[nc][0] = 0.5f * b3[8 * nc + 2 * q];
        b3c[nc][1] = 0.5f * b3[8 * nc + 2 * q + 1];
    }
    const unsigned be = 1u << (2 * q);
    const unsigned bo = be << 1;

    float v1[4][8];
    float v2[2][4];
    float v3[8][4];
#pragma unroll
    for (int ks = 0; ks < 4; ks++)
#pragma unroll
        for (int i = 0; i < 8; i++) v1[ks][i] = 0.0f;
#pragma unroll
    for (int nc = 0; nc < 2; nc++)
#pragma unroll
        for (int i = 0; i < 4; i++) v2[nc][i] = 0.0f;
#pragma unroll
    for (int nc = 0; nc < 8; nc++)
#pragma unroll
        for (int i = 0; i < 4; i++) v3[nc][i] = 0.0f;

    for (int t = 0; t < 8; t++) {
        float d2[2][4];
#pragma unroll
        for (int ks = 0; ks < 4; ks++) {
            const int c0 = 16 * ks + 2 * q;
            float2 hA0 = *(const float2*)&hs[rA][c0];
            float2 hB0 = *(const float2*)&hs[rB][c0];
            float2 hA1 = *(const float2*)&hs[rA][c0 + 8];
            float2 hB1 = *(const float2*)&hs[rB][c0 + 8];

            unsigned aw[4] = {0u, 0u, 0u, 0u};
            LIF1(v1[ks][0], hA0.x, 0x00003C00u, aw[0]);
            LIF1(v1[ks][1], hA0.y, 0x3C000000u, aw[0]);
            LIF1(v1[ks][2], hB0.x, 0x00003C00u, aw[1]);
            LIF1(v1[ks][3], hB0.y, 0x3C000000u, aw[1]);
            LIF1(v1[ks][4], hA1.x, 0x00003C00u, aw[2]);
            LIF1(v1[ks][5], hA1.y, 0x3C000000u, aw[2]);
            LIF1(v1[ks][6], hB1.x, 0x00003C00u, aw[3]);
            LIF1(v1[ks][7], hB1.y, 0x3C000000u, aw[3]);

#pragma unroll
            for (int nc = 0; nc < 2; nc++) {
                uint4 w = w2s[nc * 4 + ks][lane];
                if (ks == 0)
                    mma16816h_c(d2[nc], aw, w.x, w.y,
                                b2c[nc][0], b2c[nc][1], b2c[nc][0], b2c[nc][1]);
                else
                    mma16816h(d2[nc], aw, w.x, w.y);
                mma16816h(d2[nc], aw, w.z, w.w);
            }
        }

        unsigned s2f[4];
#pragma unroll
        for (int nc = 0; nc < 2; nc++) {
            unsigned frA = 0u, frB = 0u;
            LIF1(v2[nc][0], d2[nc][0], 0x00003C00u, frA);
            LIF1(v2[nc][1], d2[nc][1], 0x3C000000u, frA);
            LIF1(v2[nc][2], d2[nc][2], 0x00003C00u, frB);
            LIF1(v2[nc][3], d2[nc][3], 0x3C000000u, frB);
            s2f[nc * 2]     = frA;
            s2f[nc * 2 + 1] = frB;
        }

        unsigned mA0 = 0u, mA1 = 0u, mB0 = 0u, mB1 = 0u;
#pragma unroll
        for (int nc = 0; nc < 8; nc++) {
            uint4 w = w3s[nc][lane];
            float d3[4];
            mma16816h_c(d3, s2f, w.x, w.y,
                        b3c[nc][0], b3c[nc][1], b3c[nc][0], b3c[nc][1]);
            mma16816h(d3, s2f, w.z, w.w);

            const unsigned bitE = be << (8 * (nc & 3));
            const unsigned bitO = bo << (8 * (nc & 3));
            {
                float nv = fmaf(v3[nc][0], 0.5f, d3[0]);
                bool s = nv >= 1.0f; v3[nc][0] = s ? 0.0f : nv;
                if (s) { if (nc < 4) mA0 |= bitE; else mA1 |= bitE; }
            }
            {
                float nv = fmaf(v3[nc][1], 0.5f, d3[1]);
                bool s = nv >= 1.0f; v3[nc][1] = s ? 0.0f : nv;
                if (s) { if (nc < 4) mA0 |= bitO; else mA1 |= bitO; }
            }
            {
                float nv = fmaf(v3[nc][2], 0.5f, d3[2]);
                bool s = nv >= 1.0f; v3[nc][2] = s ? 0.0f : nv;
                if (s) { if (nc < 4) mB0 |= bitE; else mB1 |= bitE; }
            }
            {
                float nv = fmaf(v3[nc][3], 0.5f, d3[3]);
                bool s = nv >= 1.0f; v3[nc][3] = s ? 0.0f : nv;
                if (s) { if (nc < 4) mB0 |= bitO; else mB1 |= bitO; }
            }
        }

        mA0 |= __shfl_xor_sync(0xffffffffu, mA0, 1);
        mA1 |= __shfl_xor_sync(0xffffffffu, mA1, 1);
        mB0 |= __shfl_xor_sync(0xffffffffu, mB0, 1);
        mB1 |= __shfl_xor_sync(0xffffffffu, mB1, 1);
        mA0 |= __shfl_xor_sync(0xffffffffu, mA0, 2);
        mA1 |= __shfl_xor_sync(0xffffffffu, mA1, 2);
        mB0 |= __shfl_xor_sync(0xffffffffu, mB0, 2);
        mB1 |= __shfl_xor_sync(0xffffffffu, mB1, 2);

        if (q == 0) {
            g_masks[(size_t)(row0 + rA) * 8 + t] =
                (unsigned long long)mA0 | ((unsigned long long)mA1 << 32);
            g_masks[(size_t)(row0 + rB) * 8 + t] =
                (unsigned long long)mB0 | ((unsigned long long)mB1 << 32);
        }
    }
}

// ---------------------------------------------------------------------------
// Kernel 3: fp16 HMMA (f16 accum), warp covers 32 columns, DOUBLE-BUFFERED
// frag staging: producer fills tile it+1 while consumers run MMAs on tile it.
// One __syncthreads per iteration. Dynamic smem = 64 KB (2 buffers).
// ---------------------------------------------------------------------------
__global__ void __launch_bounds__(256) k3_mma(const float* __restrict__ b4,
                                              float* __restrict__ out) {
    extern __shared__ uint4 sfd[];
    // SF0(buf) = sfd + buf*1024 ; SF1(buf) = sfd + 2048 + buf*1024
    // index [t][cc][lane] = t*128 + cc*32 + lane

    const int tid = threadIdx.x;
    const int warp = tid >> 5, lane = tid & 31;
    const int g = lane >> 2;
    const int q = lane & 3;
    const int colbase = blockIdx.y * 256 + warp * 32;
    const int c0 = colbase + g;
    const int c2 = colbase + 16 + g;

    unsigned af0[4][4], af1[4][4];
#pragma unroll
    for (int ks = 0; ks < 4; ks++) {
        af0[ks][0] = g_w4f[c0 * 32 + ks * 8 + q];
        af0[ks][1] = g_w4f[(c0 + 8) * 32 + ks * 8 + q];
        af0[ks][2] = g_w4f[c0 * 32 + ks * 8 + 4 + q];
        af0[ks][3] = g_w4f[(c0 + 8) * 32 + ks * 8 + 4 + q];
        af1[ks][0] = g_w4f[c2 * 32 + ks * 8 + q];
        af1[ks][1] = g_w4f[(c2 + 8) * 32 + ks * 8 + q];
        af1[ks][2] = g_w4f[c2 * 32 + ks * 8 + 4 + q];
        af1[ks][3] = g_w4f[(c2 + 8) * 32 + ks * 8 + 4 + q];
    }
    __half2 h0 = __float2half2_rn(0.5f * b4[c0]);
    __half2 h1 = __float2half2_rn(0.5f * b4[c0 + 8]);
    __half2 h2 = __float2half2_rn(0.5f * b4[c2]);
    __half2 h3 = __float2half2_rn(0.5f * b4[c2 + 8]);
    const unsigned ce0 = *(unsigned*)&h0, ce1 = *(unsigned*)&h1;
    const unsigned ce2 = *(unsigned*)&h2, ce3 = *(unsigned*)&h3;

    const int bb0 = blockIdx.x * 128;

    // producer lambda-equivalent via macro
#define K3_PRODUCE(BB, BUF) {                                                 \
        uint4* s0 = sfd + (BUF) * 1024;                                       \
        uint4* s1 = sfd + 2048 + (BUF) * 1024;                                \
        _Pragma("unroll")                                                     \
        for (int cc = 0; cc < 4; cc++) {                                      \
            const unsigned long long m =                                      \
                g_masks[(size_t)((BB) + cc * 8 + g) * 8 + warp];              \
            unsigned wv[4][2];                                                \
            _Pragma("unroll")                                                 \
            for (int ks = 0; ks < 4; ks++) {                                  \
                unsigned xx = (unsigned)(m >> (ks * 16 + 2 * q));             \
                unsigned t0 = (unsigned)((int)(xx << 31) >> 31) & 0x00003C00u;\
                unsigned t1 = (unsigned)((int)(xx << 30) >> 31) & 0x3C000000u;\
                wv[ks][0] = t0 | t1;                                          \
                unsigned yy = (unsigned)(m >> (ks * 16 + 8 + 2 * q));         \
                unsigned t2 = (unsigned)((int)(yy << 31) >> 31) & 0x00003C00u;\
                unsigned t3 = (unsigned)((int)(yy << 30) >> 31) & 0x3C000000u;\
                wv[ks][1] = t2 | t3;                                          \
            }                                                                 \
            s0[warp * 128 + cc * 32 + lane] =                                 \
                make_uint4(wv[0][0], wv[0][1], wv[1][0], wv[1][1]);           \
            s1[warp * 128 + cc * 32 + lane] =                                 \
                make_uint4(wv[2][0], wv[2][1], wv[3][0], wv[3][1]);           \
        }                                                                     \
    }

    K3_PRODUCE(bb0, 0);
    __syncthreads();

    for (int it = 0; it < 4; it++) {
        const int buf = it & 1;
        if (it < 3) K3_PRODUCE(bb0 + (it + 1) * 32, 1 - buf);

        const uint4* s0 = sfd + buf * 1024;
        const uint4* s1 = sfd + 2048 + buf * 1024;
        const int bbase = bb0 + it * 32;

#pragma unroll
        for (int cc = 0; cc < 4; cc++) {
            __half2 s00 = __float2half2_rn(0.0f);
            __half2 s01 = __float2half2_rn(0.0f);
            __half2 s10 = __float2half2_rn(0.0f);
            __half2 s11 = __float2half2_rn(0.0f);
#pragma unroll
            for (int t = 0; t < 8; t++) {
                uint4 fa = s0[t * 128 + cc * 32 + lane];
                uint4 fb = s1[t * 128 + cc * 32 + lane];

                unsigned d0[2] = {ce0, ce1};
                unsigned d1[2] = {ce2, ce3};
                mma16816hh(d0, af0[0], fa.x, fa.y);
                mma16816hh(d1, af1[0], fa.x, fa.y);
                mma16816hh(d0, af0[1], fa.z, fa.w);
                mma16816hh(d1, af1[1], fa.z, fa.w);
                mma16816hh(d0, af0[2], fb.x, fb.y);
                mma16816hh(d1, af1[2], fb.x, fb.y);
                mma16816hh(d0, af0[3], fb.z, fb.w);
                mma16816hh(d1, af1[3], fb.z, fb.w);

                unsigned t00 = tanh2(d0[0]);
                unsigned t01 = tanh2(d0[1]);
                unsigned t10 = tanh2(d1[0]);
                unsigned t11 = tanh2(d1[1]);
                s00 = __hadd2(s00, *(__half2*)&t00);
                s01 = __hadd2(s01, *(__half2*)&t01);
                s10 = __hadd2(s10, *(__half2*)&t10);
                s11 = __hadd2(s11, *(__half2*)&t11);
            }
            float2 f00 = __half22float2(s00);
            float2 f01 = __half22float2(s01);
            float2 f10 = __half22float2(s10);
            float2 f11 = __half22float2(s11);
            const int b0 = bbase + cc * 8 + 2 * q;
            float* ob0 = out + (size_t)b0 * 512;
            float* ob1 = out + (size_t)(b0 + 1) * 512;
            ob0[c0]      = fmaf(f00.x, 0.0625f, 0.5f);
            ob1[c0]      = fmaf(f00.y, 0.0625f, 0.5f);
            ob0[c0 + 8]  = fmaf(f01.x, 0.0625f, 0.5f);
            ob1[c0 + 8]  = fmaf(f01.y, 0.0625f, 0.5f);
            ob0[c2]      = fmaf(f10.x, 0.0625f, 0.5f);
            ob1[c2]      = fmaf(f10.y, 0.0625f, 0.5f);
            ob0[c2 + 8]  = fmaf(f11.x, 0.0625f, 0.5f);
            ob1[c2 + 8]  = fmaf(f11.y, 0.0625f, 0.5f);
        }
        __syncthreads();
    }
#undef K3_PRODUCE
}

// ---------------------------------------------------------------------------
extern "C" void kernel_launch(void* const* d_in, const int* in_sizes, int n_in,
                              void* d_out, int out_size) {
    const float* x  = (const float*)d_in[0];
    const float* W1 = (const float*)d_in[1];
    const float* b1 = (const float*)d_in[2];
    const float* W2 = (const float*)d_in[3];
    const float* b2 = (const float*)d_in[4];
    const float* W3 = (const float*)d_in[5];
    const float* b3 = (const float*)d_in[6];
    const float* W4 = (const float*)d_in[7];
    const float* b4 = (const float*)d_in[8];
    float* out = (float*)d_out;

    static bool attr_set = false;
    if (!attr_set) {
        cudaFuncSetAttribute(k1_hin, cudaFuncAttributeMaxDynamicSharedMemorySize, 51200);
        cudaFuncSetAttribute(k3_mma, cudaFuncAttributeMaxDynamicSharedMemorySize, 65536);
        attr_set = true;
    }

    k0_pack<<<98, 256>>>(W4, W1, W2, W3);
    k1_hin<<<B_TOTAL / 128, 256, 51200>>>(x, b1);
    k2_recur<<<B_TOTAL / 64, 128>>>(b2, b3);
    k3_mma<<<dim3(B_TOTAL / 128, 2), 256, 65536>>>(b4, out);
}